// round 2
// baseline (speedup 1.0000x reference)
#include <cuda_runtime.h>

#define NB 8
#define NC 256
#define ND 128
#define NN 4096   // 64*64

// ---------------- scratch (static device globals; no allocation) ----------------
__device__ float g_qp[NB * NN * ND];                 // 16 MB  [b][n][d]
__device__ float g_kp[NB * NN * ND];                 // 16 MB
__device__ float g_vp[NB * NN * ND];                 // 16 MB
__device__ float g_av[NB * NN * ND];                 // 16 MB  attention output [b][n][d]
__device__ float g_S[(size_t)NB * NN * NN];          // 536 MB [b][n][m]
__device__ float g_cmax[NB * NN];                    // column max over n, per (b,m)
__device__ float g_rinv[NB * NN];                    // 1/column-sum

// ---------------- fast exp: FFMA-only (avoids MUFU bottleneck) -------------------
__device__ __forceinline__ float fast_exp(float x) {
    x = fmaxf(x, -87.0f);
    float t  = x * 1.4426950408889634f;      // x * log2(e)
    float fi = floorf(t);
    float f  = t - fi;
    // 2^f on [0,1): degree-5 poly, rel err ~1e-7
    float p = 1.3398874402665740e-3f;
    p = fmaf(p, f, 9.6184373576464000e-3f);
    p = fmaf(p, f, 5.5503324711628090e-2f);
    p = fmaf(p, f, 2.4022647913630120e-1f);
    p = fmaf(p, f, 6.9314720285504210e-1f);
    p = fmaf(p, f, 1.0f);
    return __int_as_float(__float_as_int(p) + (((int)fi) << 23));
}

// ---------------- shared 128x128x(Kt=8) SGEMM inner core -------------------------
// 256 threads = 16x16; thread (ty,tx) owns rows {ty*4..+3, 64+ty*4..+3} x cols
// {tx*4..+3, 64+tx*4..+3}. LDS.128 conflict-free by construction.
__device__ __forceinline__ void mm_inner(const float (*As)[132], const float (*Bs)[132],
                                         int ty, int tx, float acc[8][8]) {
#pragma unroll
    for (int kk = 0; kk < 8; kk++) {
        float4 a0 = *(const float4*)&As[kk][ty * 4];
        float4 a1 = *(const float4*)&As[kk][64 + ty * 4];
        float4 b0 = *(const float4*)&Bs[kk][tx * 4];
        float4 b1 = *(const float4*)&Bs[kk][64 + tx * 4];
        float a[8] = {a0.x, a0.y, a0.z, a0.w, a1.x, a1.y, a1.z, a1.w};
        float b[8] = {b0.x, b0.y, b0.z, b0.w, b1.x, b1.y, b1.z, b1.w};
#pragma unroll
        for (int i = 0; i < 8; i++)
#pragma unroll
            for (int j = 0; j < 8; j++)
                acc[i][j] = fmaf(a[i], b[j], acc[i][j]);
    }
}

// ================================================================================
// K1: projections. out[b,n,d] = sum_c in[b,c,n] * W[d,c]
// grid (3, NN/128, NB), block 256. rows=n(128), cols=d(128), K=C=256.
// ================================================================================
__global__ void __launch_bounds__(256) proj_kernel(
    const float* __restrict__ q, const float* __restrict__ k, const float* __restrict__ v,
    const float* __restrict__ Wt, const float* __restrict__ Wp, const float* __restrict__ Wg)
{
    int which = blockIdx.x;
    int n0    = blockIdx.y * 128;
    int b     = blockIdx.z;
    const float* in = (which == 0) ? q  : (which == 1) ? k  : v;
    const float* Wm = (which == 0) ? Wt : (which == 1) ? Wp : Wg;
    float*      out = (which == 0) ? g_qp : (which == 1) ? g_kp : g_vp;

    __shared__ float As[8][132];   // [c-kk][n]
    __shared__ float Bs[8][132];   // [c-kk][d]
    int tid = threadIdx.x;
    int ty = tid >> 4, tx = tid & 15;
    float acc[8][8] = {};

    int akk = tid >> 5;           // 0..7   A loader: row of in (a c value)
    int anp = (tid & 31) << 2;    // 0..124 n offset
    int bd  = tid >> 1;           // 0..127 B loader: d
    int bcp = (tid & 1) << 2;     // 0 or 4 c offset
    const float* inb = in + ((size_t)b * NC) * NN + n0;

    for (int c0 = 0; c0 < NC; c0 += 8) {
        float4 av = *(const float4*)(inb + (size_t)(c0 + akk) * NN + anp);
        *(float4*)&As[akk][anp] = av;
        float4 wv = *(const float4*)(Wm + (size_t)bd * NC + c0 + bcp);
        Bs[bcp + 0][bd] = wv.x; Bs[bcp + 1][bd] = wv.y;
        Bs[bcp + 2][bd] = wv.z; Bs[bcp + 3][bd] = wv.w;
        __syncthreads();
        mm_inner(As, Bs, ty, tx, acc);
        __syncthreads();
    }

    float* ob = out + ((size_t)b * NN + n0) * ND;
#pragma unroll
    for (int i = 0; i < 8; i++) {
        int r = ((i >> 2) << 6) + ty * 4 + (i & 3);
        float4 w0 = {acc[i][0], acc[i][1], acc[i][2], acc[i][3]};
        float4 w1 = {acc[i][4], acc[i][5], acc[i][6], acc[i][7]};
        *(float4*)(ob + (size_t)r * ND + tx * 4)      = w0;
        *(float4*)(ob + (size_t)r * ND + 64 + tx * 4) = w1;
    }
}

// ================================================================================
// K2: S[b,n,m] = (1/sqrt(D)) * sum_d qp[b,n,d] * kp[b,m,d]
// grid (NN/128 m-tiles, NN/128 n-tiles, NB), block 256.
// ================================================================================
__global__ void __launch_bounds__(256) s_kernel()
{
    int m0 = blockIdx.x * 128;
    int n0 = blockIdx.y * 128;
    int b  = blockIdx.z;
    const float* qb = g_qp + (size_t)b * NN * ND;
    const float* kb = g_kp + (size_t)b * NN * ND;

    __shared__ float As[8][132];   // [d-kk][n]
    __shared__ float Bs[8][132];   // [d-kk][m]
    int tid = threadIdx.x;
    int ty = tid >> 4, tx = tid & 15;
    float acc[8][8] = {};
    int lr = tid >> 1;            // 0..127
    int lp = (tid & 1) << 2;      // 0 or 4

    for (int d0 = 0; d0 < ND; d0 += 8) {
        float4 qv = *(const float4*)(qb + (size_t)(n0 + lr) * ND + d0 + lp);
        float4 kv = *(const float4*)(kb + (size_t)(m0 + lr) * ND + d0 + lp);
        As[lp + 0][lr] = qv.x; As[lp + 1][lr] = qv.y; As[lp + 2][lr] = qv.z; As[lp + 3][lr] = qv.w;
        Bs[lp + 0][lr] = kv.x; Bs[lp + 1][lr] = kv.y; Bs[lp + 2][lr] = kv.z; Bs[lp + 3][lr] = kv.w;
        __syncthreads();
        mm_inner(As, Bs, ty, tx, acc);
        __syncthreads();
    }

    const float sc = 0.08838834764831845f;   // 1/sqrt(128)
    float* Sb = g_S + (size_t)b * NN * NN + (size_t)n0 * NN + m0;
#pragma unroll
    for (int i = 0; i < 8; i++) {
        int r = ((i >> 2) << 6) + ty * 4 + (i & 3);
        float4 w0 = {acc[i][0] * sc, acc[i][1] * sc, acc[i][2] * sc, acc[i][3] * sc};
        float4 w1 = {acc[i][4] * sc, acc[i][5] * sc, acc[i][6] * sc, acc[i][7] * sc};
        *(float4*)(Sb + (size_t)r * NN + tx * 4)      = w0;
        *(float4*)(Sb + (size_t)r * NN + 64 + tx * 4) = w1;
    }
}

// ================================================================================
// K3: column softmax stats over n (axis=1!). One thread per column m, streaming.
// grid (NN/256, NB), block 256.
// ================================================================================
__global__ void __launch_bounds__(256) stats_kernel()
{
    int b = blockIdx.y;
    int m = blockIdx.x * 256 + threadIdx.x;
    const float* Sb = g_S + (size_t)b * NN * NN + m;
    float mx = -1e30f, sum = 0.0f;
#pragma unroll 8
    for (int n = 0; n < NN; n++) {
        float x = Sb[(size_t)n * NN];
        if (x > mx) {                       // rare after warmup
            sum = sum * fast_exp(mx - x) + 1.0f;
            mx  = x;
        } else {
            sum += fast_exp(x - mx);
        }
    }
    g_cmax[b * NN + m] = mx;
    g_rinv[b * NN + m] = 1.0f / sum;
}

// ================================================================================
// K4: out[b,n,d] = sum_m exp(S[n,m]-cmax[m])*rinv[m] * vp[m,d]
// grid (NN/128 n-tiles, NB), block 256. K = NN = 4096, exp fused into A loader.
// ================================================================================
__global__ void __launch_bounds__(256) pv_kernel()
{
    int n0 = blockIdx.x * 128;
    int b  = blockIdx.y;
    const float* Sb = g_S   + (size_t)b * NN * NN;
    const float* vb = g_vp  + (size_t)b * NN * ND;
    const float* cm = g_cmax + (size_t)b * NN;
    const float* rv = g_rinv + (size_t)b * NN;

    __shared__ float As[8][132];   // P: [m-kk][n]
    __shared__ float Bs[8][132];   // v: [m-kk][d]
    int tid = threadIdx.x;
    int ty = tid >> 4, tx = tid & 15;
    float acc[8][8] = {};
    int lr = tid >> 1;            // P loader: n row
    int lp = (tid & 1) << 2;      // m offset
    int vk = tid >> 5;            // v loader: m row (0..7)
    int vd = (tid & 31) << 2;     // d offset

    for (int m0 = 0; m0 < NN; m0 += 8) {
        float4 sv = *(const float4*)(Sb + (size_t)(n0 + lr) * NN + m0 + lp);
        float4 c4 = *(const float4*)(cm + m0 + lp);
        float4 r4 = *(const float4*)(rv + m0 + lp);
        As[lp + 0][lr] = fast_exp(sv.x - c4.x) * r4.x;
        As[lp + 1][lr] = fast_exp(sv.y - c4.y) * r4.y;
        As[lp + 2][lr] = fast_exp(sv.z - c4.z) * r4.z;
        As[lp + 3][lr] = fast_exp(sv.w - c4.w) * r4.w;
        *(float4*)&Bs[vk][vd] = *(const float4*)(vb + (size_t)(m0 + vk) * ND + vd);
        __syncthreads();
        mm_inner(As, Bs, ty, tx, acc);
        __syncthreads();
    }

    float* ob = g_av + ((size_t)b * NN + n0) * ND;
#pragma unroll
    for (int i = 0; i < 8; i++) {
        int r = ((i >> 2) << 6) + ty * 4 + (i & 3);
        float4 w0 = {acc[i][0], acc[i][1], acc[i][2], acc[i][3]};
        float4 w1 = {acc[i][4], acc[i][5], acc[i][6], acc[i][7]};
        *(float4*)(ob + (size_t)r * ND + tx * 4)      = w0;
        *(float4*)(ob + (size_t)r * ND + 64 + tx * 4) = w1;
    }
}

// ================================================================================
// K5: y[b,c,n] = v[b,c,n] + sum_d g_av[b,n,d] * W_out[c,d]
// grid (NN/128 n-tiles, NC/128 c-tiles, NB), block 256. rows=c, cols=n, K=D.
// ================================================================================
__global__ void __launch_bounds__(256) final_kernel(const float* __restrict__ vin,
                                                    const float* __restrict__ Wo,
                                                    float* __restrict__ y)
{
    int n0 = blockIdx.x * 128;
    int c0 = blockIdx.y * 128;
    int b  = blockIdx.z;
    const float* ob = g_av + (size_t)b * NN * ND;

    __shared__ float As[8][132];   // [d-kk][c]
    __shared__ float Bs[8][132];   // [d-kk][n]
    int tid = threadIdx.x;
    int ty = tid >> 4, tx = tid & 15;
    float acc[8][8] = {};
    int lr = tid >> 1;
    int lp = (tid & 1) << 2;

    for (int d0 = 0; d0 < ND; d0 += 8) {
        float4 wv = *(const float4*)(Wo + (size_t)(c0 + lr) * ND + d0 + lp);
        float4 ov = *(const float4*)(ob + (size_t)(n0 + lr) * ND + d0 + lp);
        As[lp + 0][lr] = wv.x; As[lp + 1][lr] = wv.y; As[lp + 2][lr] = wv.z; As[lp + 3][lr] = wv.w;
        Bs[lp + 0][lr] = ov.x; Bs[lp + 1][lr] = ov.y; Bs[lp + 2][lr] = ov.z; Bs[lp + 3][lr] = ov.w;
        __syncthreads();
        mm_inner(As, Bs, ty, tx, acc);
        __syncthreads();
    }

    const float* vb = vin + ((size_t)b * NC + c0) * NN + n0;
    float*       yb = y   + ((size_t)b * NC + c0) * NN + n0;
#pragma unroll
    for (int i = 0; i < 8; i++) {
        int r = ((i >> 2) << 6) + ty * 4 + (i & 3);
        float4 v0 = *(const float4*)(vb + (size_t)r * NN + tx * 4);
        float4 v1 = *(const float4*)(vb + (size_t)r * NN + 64 + tx * 4);
        float4 w0 = {acc[i][0] + v0.x, acc[i][1] + v0.y, acc[i][2] + v0.z, acc[i][3] + v0.w};
        float4 w1 = {acc[i][4] + v1.x, acc[i][5] + v1.y, acc[i][6] + v1.z, acc[i][7] + v1.w};
        *(float4*)(yb + (size_t)r * NN + tx * 4)      = w0;
        *(float4*)(yb + (size_t)r * NN + 64 + tx * 4) = w1;
    }
}

// ================================================================================
extern "C" void kernel_launch(void* const* d_in, const int* in_sizes, int n_in,
                              void* d_out, int out_size)
{
    const float* q  = (const float*)d_in[0];
    const float* k  = (const float*)d_in[1];
    const float* v  = (const float*)d_in[2];
    const float* Wt = (const float*)d_in[3];
    const float* Wp = (const float*)d_in[4];
    const float* Wg = (const float*)d_in[5];
    const float* Wo = (const float*)d_in[6];
    float* y = (float*)d_out;

    proj_kernel <<<dim3(3, NN / 128, NB), 256>>>(q, k, v, Wt, Wp, Wg);
    s_kernel    <<<dim3(NN / 128, NN / 128, NB), 256>>>();
    stats_kernel<<<dim3(NN / 256, NB), 256>>>();
    pv_kernel   <<<dim3(NN / 128, NB), 256>>>();
    final_kernel<<<dim3(NN / 128, NC / 128, NB), 256>>>(v, Wo, y);
}

// round 4
// speedup vs baseline: 6.2666x; 6.2666x over previous
#include <cuda_runtime.h>
#include <cuda_bf16.h>
#include <cstdint>

#define NB 8
#define NC 256
#define ND 128
#define NN 4096   // 64*64

// ---------------- scratch (static device globals; no allocation) ----------------
__device__ __nv_bfloat16 g_qp[(size_t)NB * NN * ND];      // 8 MB, pre-scaled by 1/sqrt(D)
__device__ __nv_bfloat16 g_kp[(size_t)NB * NN * ND];      // 8 MB
__device__ float         g_vp[(size_t)NB * NN * ND];      // 16 MB fp32 [b][m][d]
__device__ __nv_bfloat16 g_vpT[(size_t)NB * ND * NN];     // 8 MB  [b][d][m] = vp*rinv
__device__ float         g_av[(size_t)NB * NN * ND];      // 16 MB attention out [b][n][d]
__device__ __nv_bfloat16 g_E[(size_t)NB * NN * NN];       // 268 MB E = exp(S) [b][n][m]
__device__ float         g_sum[NB * NN];                  // column sums of E
__device__ float         g_rinv[NB * NN];

// ---------------- fast exp (FFMA-only, magic-constant round) ---------------------
__device__ __forceinline__ float fexp(float x) {
    x = fmaxf(x, -30.0f);
    float t  = fmaf(x, 1.4426950408889634f, 12582912.0f);
    int   i  = __float_as_int(t);
    float fi = t - 12582912.0f;
    float f  = fmaf(x, 1.4426950408889634f, -fi);          // [-0.5, 0.5]
    float p  = 9.6181291e-3f;
    p = fmaf(p, f, 5.5504109e-2f);
    p = fmaf(p, f, 2.4022651e-1f);
    p = fmaf(p, f, 6.9314718e-1f);
    p = fmaf(p, f, 1.0f);
    return __int_as_float(__float_as_int(p) + (i << 23));
}
__device__ __forceinline__ uint32_t pack_bf2(float a, float b) {
    __nv_bfloat162 h = __floats2bfloat162_rn(a, b);
    return *reinterpret_cast<uint32_t*>(&h);
}

// ---------------- warp-level bf16 mma (sm_80+ PTX; HMMA on sm_103) ---------------
__device__ __forceinline__ void mma16816(float* d,
                                         uint32_t a0, uint32_t a1, uint32_t a2, uint32_t a3,
                                         uint32_t b0, uint32_t b1) {
    asm volatile(
        "mma.sync.aligned.m16n8k16.row.col.f32.bf16.bf16.f32 "
        "{%0,%1,%2,%3}, {%4,%5,%6,%7}, {%8,%9}, {%0,%1,%2,%3};"
        : "+f"(d[0]), "+f"(d[1]), "+f"(d[2]), "+f"(d[3])
        : "r"(a0), "r"(a1), "r"(a2), "r"(a3), "r"(b0), "r"(b1));
}

// smem tile geometry: 128 rows x 64 bf16 (Kc) + 8 pad -> 36 words/row (bank shift 4)
#define KW 36
#define TILE_W (128 * KW)        // words per tile

// ---------------- fp32 128x128x8 SGEMM inner core (proj/final) -------------------
__device__ __forceinline__ void mm_inner(const float (*As)[132], const float (*Bs)[132],
                                         int ty, int tx, float acc[8][8]) {
#pragma unroll
    for (int kk = 0; kk < 8; kk++) {
        float4 a0 = *(const float4*)&As[kk][ty * 4];
        float4 a1 = *(const float4*)&As[kk][64 + ty * 4];
        float4 b0 = *(const float4*)&Bs[kk][tx * 4];
        float4 b1 = *(const float4*)&Bs[kk][64 + tx * 4];
        float a[8] = {a0.x, a0.y, a0.z, a0.w, a1.x, a1.y, a1.z, a1.w};
        float b[8] = {b0.x, b0.y, b0.z, b0.w, b1.x, b1.y, b1.z, b1.w};
#pragma unroll
        for (int i = 0; i < 8; i++)
#pragma unroll
            for (int j = 0; j < 8; j++)
                acc[i][j] = fmaf(a[i], b[j], acc[i][j]);
    }
}

// ================================================================================
// K1: projections. qp/kp -> bf16 (qp pre-scaled by 1/sqrt(D)), vp -> fp32
// ================================================================================
__global__ void __launch_bounds__(256) proj_kernel(
    const float* __restrict__ q, const float* __restrict__ k, const float* __restrict__ v,
    const float* __restrict__ Wt, const float* __restrict__ Wp, const float* __restrict__ Wg)
{
    int which = blockIdx.x;
    int n0    = blockIdx.y * 128;
    int b     = blockIdx.z;
    const float* in = (which == 0) ? q  : (which == 1) ? k  : v;
    const float* Wm = (which == 0) ? Wt : (which == 1) ? Wp : Wg;

    __shared__ float As[8][132];
    __shared__ float Bs[8][132];
    int tid = threadIdx.x;
    int ty = tid >> 4, tx = tid & 15;
    float acc[8][8] = {};

    int akk = tid >> 5;
    int anp = (tid & 31) << 2;
    int bd  = tid >> 1;
    int bcp = (tid & 1) << 2;
    const float* inb = in + ((size_t)b * NC) * NN + n0;

    for (int c0 = 0; c0 < NC; c0 += 8) {
        *(float4*)&As[akk][anp] = *(const float4*)(inb + (size_t)(c0 + akk) * NN + anp);
        float4 wv = *(const float4*)(Wm + (size_t)bd * NC + c0 + bcp);
        Bs[bcp + 0][bd] = wv.x; Bs[bcp + 1][bd] = wv.y;
        Bs[bcp + 2][bd] = wv.z; Bs[bcp + 3][bd] = wv.w;
        __syncthreads();
        mm_inner(As, Bs, ty, tx, acc);
        __syncthreads();
    }

    if (which == 2) {
        float* ob = g_vp + ((size_t)b * NN + n0) * ND;
#pragma unroll
        for (int i = 0; i < 8; i++) {
            int r = ((i >> 2) << 6) + ty * 4 + (i & 3);
            float4 w0 = {acc[i][0], acc[i][1], acc[i][2], acc[i][3]};
            float4 w1 = {acc[i][4], acc[i][5], acc[i][6], acc[i][7]};
            *(float4*)(ob + (size_t)r * ND + tx * 4)      = w0;
            *(float4*)(ob + (size_t)r * ND + 64 + tx * 4) = w1;
        }
    } else {
        const float s = (which == 0) ? 0.08838834764831845f : 1.0f;   // 1/sqrt(128)
        __nv_bfloat16* ob = ((which == 0) ? g_qp : g_kp) + ((size_t)b * NN + n0) * ND;
#pragma unroll
        for (int i = 0; i < 8; i++) {
            int r = ((i >> 2) << 6) + ty * 4 + (i & 3);
            *(__nv_bfloat162*)(ob + (size_t)r * ND + tx * 4)          = __floats2bfloat162_rn(acc[i][0] * s, acc[i][1] * s);
            *(__nv_bfloat162*)(ob + (size_t)r * ND + tx * 4 + 2)      = __floats2bfloat162_rn(acc[i][2] * s, acc[i][3] * s);
            *(__nv_bfloat162*)(ob + (size_t)r * ND + 64 + tx * 4)     = __floats2bfloat162_rn(acc[i][4] * s, acc[i][5] * s);
            *(__nv_bfloat162*)(ob + (size_t)r * ND + 64 + tx * 4 + 2) = __floats2bfloat162_rn(acc[i][6] * s, acc[i][7] * s);
        }
    }
}

// ================================================================================
// K2: E[b,n,m] = exp( qp[b,n,:] . kp[b,m,:] )   (mma.sync bf16, exp in epilogue)
// grid (32 m-tiles, 32 n-tiles, NB), 256 threads = 8 warps (2 x 4 warp grid)
// ================================================================================
__global__ void __launch_bounds__(256, 2) s_kernel()
{
    __shared__ uint32_t SM[2 * TILE_W];            // A | B, reused as bf16 stage
    uint32_t* Asm = SM;
    uint32_t* Bsm = SM + TILE_W;

    int tid = threadIdx.x;
    int wid = tid >> 5, lane = tid & 31;
    int wm = wid & 1, wn = wid >> 1;
    int lr = lane >> 2, lk = lane & 3;
    int m0 = blockIdx.x * 128, n0 = blockIdx.y * 128, b = blockIdx.z;
    const __nv_bfloat16* qb = g_qp + (size_t)b * NN * ND;
    const __nv_bfloat16* kb = g_kp + (size_t)b * NN * ND;

    float acc[4][4][4] = {};

    int lrow = tid >> 1;            // loader: 2 threads/row, each 1 uint4 (8 bf16)
    int lq   = tid & 1;             // which 32-bf16 half... (64 cols = 8 uint4; use idx map)

#pragma unroll
    for (int kc = 0; kc < ND; kc += 64) {
        // load A[128][64], B[128][64] (8 bf16 per thread-iter, 4 iters each)
#pragma unroll
        for (int i = 0; i < 4; i++) {
            int idx = tid + i * 256;            // 0..1023
            int row = idx >> 3, q = idx & 7;    // q: uint4 within row
            *(uint4*)&Asm[row * KW + q * 4] = *(const uint4*)(qb + (size_t)(n0 + row) * ND + kc + q * 8);
            *(uint4*)&Bsm[row * KW + q * 4] = *(const uint4*)(kb + (size_t)(m0 + row) * ND + kc + q * 8);
        }
        __syncthreads();

#pragma unroll
        for (int ks = 0; ks < 4; ks++) {
            int k0w = ks * 8;
            uint32_t a[4][4], bb[4][2];
#pragma unroll
            for (int ma = 0; ma < 4; ma++) {
                int w = (wm * 64 + ma * 16 + lr) * KW + k0w + lk;
                a[ma][0] = Asm[w];            a[ma][1] = Asm[w + 8 * KW];
                a[ma][2] = Asm[w + 4];        a[ma][3] = Asm[w + 8 * KW + 4];
            }
#pragma unroll
            for (int na = 0; na < 4; na++) {
                int w = (wn * 32 + na * 8 + lr) * KW + k0w + lk;
                bb[na][0] = Bsm[w];           bb[na][1] = Bsm[w + 4];
            }
#pragma unroll
            for (int ma = 0; ma < 4; ma++)
#pragma unroll
                for (int na = 0; na < 4; na++)
                    mma16816(acc[ma][na], a[ma][0], a[ma][1], a[ma][2], a[ma][3],
                             bb[na][0], bb[na][1]);
        }
        __syncthreads();
    }

    // epilogue: exp -> bf16 -> smem stage (stride 68 words, bank-shift 4) -> store
    uint32_t* stage = SM;                      // 128 * 68 = 8704 words < 2*TILE_W
#pragma unroll
    for (int ma = 0; ma < 4; ma++) {
        int r0 = wm * 64 + ma * 16 + lr;
#pragma unroll
        for (int na = 0; na < 4; na++) {
            int cw = wn * 16 + na * 4 + lk;    // word col
            stage[r0 * 68 + cw]       = pack_bf2(fexp(acc[ma][na][0]), fexp(acc[ma][na][1]));
            stage[(r0 + 8) * 68 + cw] = pack_bf2(fexp(acc[ma][na][2]), fexp(acc[ma][na][3]));
        }
    }
    __syncthreads();
    uint4* gE4 = (uint4*)g_E;
#pragma unroll
    for (int i = 0; i < 8; i++) {
        int idx = tid + i * 256;               // 0..2047
        int row = idx >> 4, q = idx & 15;      // 16 uint4 per row (128 bf16)
        gE4[((size_t)(b * NN + n0 + row) << 9) + (m0 >> 3) + q] =
            *(uint4*)&stage[row * 68 + q * 4];
    }
}

// ================================================================================
// K3: column sums of E over n -> g_sum  (atomicAdd partials, g_sum pre-zeroed)
// ================================================================================
__global__ void __launch_bounds__(256) stats_kernel()
{
    int b = blockIdx.z;
    int w = blockIdx.x * 256 + threadIdx.x;      // word index over m (2 cols)
    int n0 = blockIdx.y * 512;
    const __nv_bfloat162* p = ((const __nv_bfloat162*)g_E) + ((size_t)(b * NN + n0)) * (NN / 2) + w;
    float s0 = 0.0f, s1 = 0.0f;
#pragma unroll 8
    for (int n = 0; n < 512; n++) {
        float2 f = __bfloat1622float2(p[(size_t)n * (NN / 2)]);
        s0 += f.x; s1 += f.y;
    }
    atomicAdd(&g_sum[b * NN + 2 * w], s0);
    atomicAdd(&g_sum[b * NN + 2 * w + 1], s1);
}

__global__ void __launch_bounds__(256) rinv_kernel()
{
    int i = blockIdx.x * 256 + threadIdx.x;
    g_rinv[i] = 1.0f / g_sum[i];
}

// ================================================================================
// K4: vpT[b,d,m] = bf16( vp[b,m,d] * rinv[b,m] )   (32x32 smem transpose)
// ================================================================================
__global__ void __launch_bounds__(256) vps_kernel()
{
    __shared__ float t[32][33];
    int b = blockIdx.z, m0 = blockIdx.x * 32, d0 = blockIdx.y * 32;
    const float* vb = g_vp + (size_t)b * NN * ND;
    const float* rv = g_rinv + b * NN;
    int tx = threadIdx.x, ty = threadIdx.y;
#pragma unroll
    for (int i = 0; i < 4; i++) {
        int m = m0 + ty + i * 8;
        t[ty + i * 8][tx] = vb[(size_t)m * ND + d0 + tx] * rv[m];
    }
    __syncthreads();
    __nv_bfloat16* ob = g_vpT + (size_t)b * ND * NN;
#pragma unroll
    for (int i = 0; i < 4; i++) {
        int d = d0 + ty + i * 8;
        ob[(size_t)d * NN + m0 + tx] = __float2bfloat16(t[tx][ty + i * 8]);
    }
}

// ================================================================================
// K5: av[b,n,d] = sum_m E[b,n,m] * vpT[b,d,m]   (mma.sync bf16, K=4096)
// grid (32 n-tiles, NB), 256 threads
// ================================================================================
__global__ void __launch_bounds__(256, 2) pv_kernel()
{
    __shared__ uint32_t SM[2 * TILE_W];
    uint32_t* Asm = SM;
    uint32_t* Bsm = SM + TILE_W;

    int tid = threadIdx.x;
    int wid = tid >> 5, lane = tid & 31;
    int wm = wid & 1, wn = wid >> 1;
    int lr = lane >> 2, lk = lane & 3;
    int n0 = blockIdx.x * 128, b = blockIdx.y;
    const __nv_bfloat16* Eb = g_E   + (size_t)b * NN * NN;
    const __nv_bfloat16* vt = g_vpT + (size_t)b * ND * NN;

    float acc[4][4][4] = {};

    for (int m0 = 0; m0 < NN; m0 += 64) {
#pragma unroll
        for (int i = 0; i < 4; i++) {
            int idx = tid + i * 256;
            int row = idx >> 3, q = idx & 7;
            *(uint4*)&Asm[row * KW + q * 4] = *(const uint4*)(Eb + (size_t)(n0 + row) * NN + m0 + q * 8);
            *(uint4*)&Bsm[row * KW + q * 4] = *(const uint4*)(vt + (size_t)row * NN + m0 + q * 8);
        }
        __syncthreads();

#pragma unroll
        for (int ks = 0; ks < 4; ks++) {
            int k0w = ks * 8;
            uint32_t a[4][4], bb[4][2];
#pragma unroll
            for (int ma = 0; ma < 4; ma++) {
                int w = (wm * 64 + ma * 16 + lr) * KW + k0w + lk;
                a[ma][0] = Asm[w];            a[ma][1] = Asm[w + 8 * KW];
                a[ma][2] = Asm[w + 4];        a[ma][3] = Asm[w + 8 * KW + 4];
            }
#pragma unroll
            for (int na = 0; na < 4; na++) {
                int w = (wn * 32 + na * 8 + lr) * KW + k0w + lk;
                bb[na][0] = Bsm[w];           bb[na][1] = Bsm[w + 4];
            }
#pragma unroll
            for (int ma = 0; ma < 4; ma++)
#pragma unroll
                for (int na = 0; na < 4; na++)
                    mma16816(acc[ma][na], a[ma][0], a[ma][1], a[ma][2], a[ma][3],
                             bb[na][0], bb[na][1]);
        }
        __syncthreads();
    }

    // epilogue: direct float2 stores (4 lanes x 8B = full 32B sectors)
    float* ob = g_av + ((size_t)b * NN + n0) * ND;
#pragma unroll
    for (int ma = 0; ma < 4; ma++) {
        int r0 = wm * 64 + ma * 16 + lr;
#pragma unroll
        for (int na = 0; na < 4; na++) {
            int c = wn * 32 + na * 8 + lk * 2;
            *(float2*)(ob + (size_t)r0 * ND + c)       = make_float2(acc[ma][na][0], acc[ma][na][1]);
            *(float2*)(ob + (size_t)(r0 + 8) * ND + c) = make_float2(acc[ma][na][2], acc[ma][na][3]);
        }
    }
}

// ================================================================================
// K6: y[b,c,n] = v[b,c,n] + sum_d av[b,n,d] * W_out[c,d]
// ================================================================================
__global__ void __launch_bounds__(256) final_kernel(const float* __restrict__ vin,
                                                    const float* __restrict__ Wo,
                                                    float* __restrict__ y)
{
    int n0 = blockIdx.x * 128;
    int c0 = blockIdx.y * 128;
    int b  = blockIdx.z;
    const float* ob = g_av + (size_t)b * NN * ND;

    __shared__ float As[8][132];
    __shared__ float Bs[8][132];
    int tid = threadIdx.x;
    int ty = tid >> 4, tx = tid & 15;
    float acc[8][8] = {};
    int lr = tid >> 1;
    int lp = (tid & 1) << 2;

    for (int d0 = 0; d0 < ND; d0 += 8) {
        float4 wv = *(const float4*)(Wo + (size_t)(c0 + lr) * ND + d0 + lp);
        float4 ov = *(const float4*)(ob + (size_t)(n0 + lr) * ND + d0 + lp);
        As[lp + 0][lr] = wv.x; As[lp + 1][lr] = wv.y; As[lp + 2][lr] = wv.z; As[lp + 3][lr] = wv.w;
        Bs[lp + 0][lr] = ov.x; Bs[lp + 1][lr] = ov.y; Bs[lp + 2][lr] = ov.z; Bs[lp + 3][lr] = ov.w;
        __syncthreads();
        mm_inner(As, Bs, ty, tx, acc);
        __syncthreads();
    }

    const float* vb = vin + ((size_t)b * NC + c0) * NN + n0;
    float*       yb = y   + ((size_t)b * NC + c0) * NN + n0;
#pragma unroll
    for (int i = 0; i < 8; i++) {
        int r = ((i >> 2) << 6) + ty * 4 + (i & 3);
        float4 v0 = *(const float4*)(vb + (size_t)r * NN + tx * 4);
        float4 v1 = *(const float4*)(vb + (size_t)r * NN + 64 + tx * 4);
        float4 w0 = {acc[i][0] + v0.x, acc[i][1] + v0.y, acc[i][2] + v0.z, acc[i][3] + v0.w};
        float4 w1 = {acc[i][4] + v1.x, acc[i][5] + v1.y, acc[i][6] + v1.z, acc[i][7] + v1.w};
        *(float4*)(yb + (size_t)r * NN + tx * 4)      = w0;
        *(float4*)(yb + (size_t)r * NN + 64 + tx * 4) = w1;
    }
}

// ================================================================================
extern "C" void kernel_launch(void* const* d_in, const int* in_sizes, int n_in,
                              void* d_out, int out_size)
{
    const float* q  = (const float*)d_in[0];
    const float* k  = (const float*)d_in[1];
    const float* v  = (const float*)d_in[2];
    const float* Wt = (const float*)d_in[3];
    const float* Wp = (const float*)d_in[4];
    const float* Wg = (const float*)d_in[5];
    const float* Wo = (const float*)d_in[6];
    float* y = (float*)d_out;

    void* sumAddr = nullptr;
    cudaGetSymbolAddress(&sumAddr, g_sum);
    cudaMemsetAsync(sumAddr, 0, NB * NN * sizeof(float));

    proj_kernel <<<dim3(3, NN / 128, NB), 256>>>(q, k, v, Wt, Wp, Wg);
    s_kernel    <<<dim3(NN / 128, NN / 128, NB), 256>>>();
    stats_kernel<<<dim3(NN / 512, 8, NB), 256>>>();
    rinv_kernel <<<dim3(NB * NN / 256), 256>>>();
    vps_kernel  <<<dim3(NN / 32, ND / 32, NB), dim3(32, 8)>>>();
    pv_kernel   <<<dim3(NN / 128, NB), 256>>>();
    final_kernel<<<dim3(NN / 128, NC / 128, NB), 256>>>(v, Wo, y);
}

// round 6
// speedup vs baseline: 10.3108x; 1.6453x over previous
#include <cuda_runtime.h>
#include <cuda_bf16.h>
#include <cstdint>

#define NB 8
#define NC 256
#define ND 128
#define NN 4096   // 64*64

// ---------------- scratch (static device globals; no allocation) ----------------
__device__ __nv_bfloat16 g_qpT[(size_t)NB * ND * NN];     // 8 MB [b][d][n], pre-scaled 1/sqrt(D)
__device__ __nv_bfloat16 g_kpT[(size_t)NB * ND * NN];     // 8 MB [b][d][m]
__device__ __nv_bfloat16 g_vpT[(size_t)NB * ND * NN];     // 8 MB [b][d][m]; later *= rinv[m]
__device__ __nv_bfloat16 g_avh[(size_t)NB * NN * ND];     // 8 MB attention out [b][n][d]
__device__ __nv_bfloat16 g_E[(size_t)NB * NN * NN];       // 268 MB E = exp(S) [b][n][m]
__device__ float         g_sum[NB * NN];                  // column sums of E over n
__device__ float         g_rinv[NB * NN];

// ---------------- fast exp (FFMA-only) -------------------------------------------
__device__ __forceinline__ float fexp(float x) {
    x = fmaxf(x, -30.0f);
    float t  = fmaf(x, 1.4426950408889634f, 12582912.0f);
    int   i  = __float_as_int(t);
    float fi = t - 12582912.0f;
    float f  = fmaf(x, 1.4426950408889634f, -fi);
    float p  = 9.6181291e-3f;
    p = fmaf(p, f, 5.5504109e-2f);
    p = fmaf(p, f, 2.4022651e-1f);
    p = fmaf(p, f, 6.9314718e-1f);
    p = fmaf(p, f, 1.0f);
    return __int_as_float(__float_as_int(p) + (i << 23));
}
__device__ __forceinline__ uint32_t pack_bf2(float a, float b) {
    __nv_bfloat162 h = __floats2bfloat162_rn(a, b);
    return *reinterpret_cast<uint32_t*>(&h);
}

// ---------------- HMMA + ldmatrix + cp.async helpers -----------------------------
__device__ __forceinline__ void mma16816(float* d,
                                         uint32_t a0, uint32_t a1, uint32_t a2, uint32_t a3,
                                         uint32_t b0, uint32_t b1) {
    asm volatile(
        "mma.sync.aligned.m16n8k16.row.col.f32.bf16.bf16.f32 "
        "{%0,%1,%2,%3}, {%4,%5,%6,%7}, {%8,%9}, {%0,%1,%2,%3};"
        : "+f"(d[0]), "+f"(d[1]), "+f"(d[2]), "+f"(d[3])
        : "r"(a0), "r"(a1), "r"(a2), "r"(a3), "r"(b0), "r"(b1));
}
__device__ __forceinline__ void ldsm4t(uint32_t addr, uint32_t* r) {
    asm volatile("ldmatrix.sync.aligned.m8n8.x4.trans.shared.b16 {%0,%1,%2,%3}, [%4];"
                 : "=r"(r[0]), "=r"(r[1]), "=r"(r[2]), "=r"(r[3]) : "r"(addr));
}
__device__ __forceinline__ void cpa16(uint32_t dst, const void* src) {
    asm volatile("cp.async.cg.shared.global [%0], [%1], 16;" :: "r"(dst), "l"(src) : "memory");
}
#define CP_COMMIT() asm volatile("cp.async.commit_group;" ::: "memory")
#define CP_WAIT(n)  asm volatile("cp.async.wait_group %0;" :: "n"(n) : "memory")
__device__ __forceinline__ uint32_t smem_u32(const void* p) {
    return (uint32_t)__cvta_generic_to_shared(p);
}

// smem row strides (words): 128 bf16 + 8 pad = 68 (≡4 mod 32, conflict-free frag loads)
#define KW128 68
#define TILE128 (128 * KW128)     // 8704 words = 34816 B
// pv chunk: 64 bf16 + 8 pad = 36 words
#define KW64 36
#define TILE64 (128 * KW64)       // 4608 words

// ================================================================================
// K1: projections -> TRANSPOSED outputs [d][n].
//   out[d][n] = sum_c W[d][c] * in[c][n];  A = W (fp32->bf16), B = in (fp32->bf16),
//   b-frags via ldmatrix.trans from [c][n] storage.  grid (3, 32 n-tiles, NB).
// ================================================================================
__global__ void __launch_bounds__(256, 2) proj_kernel(
    const float* __restrict__ q, const float* __restrict__ k, const float* __restrict__ v,
    const float* __restrict__ Wt, const float* __restrict__ Wp, const float* __restrict__ Wg)
{
    extern __shared__ uint32_t dsm[];
    uint32_t* Asm = dsm;              // W tile  [d=128][c=128]
    uint32_t* Bsm = dsm + TILE128;    // in tile [c=128][n=128]

    int which = blockIdx.x;
    int n0    = blockIdx.y * 128;
    int b     = blockIdx.z;
    const float* in = (which == 0) ? q  : (which == 1) ? k  : v;
    const float* Wm = (which == 0) ? Wt : (which == 1) ? Wp : Wg;
    __nv_bfloat16* outp = (which == 0) ? g_qpT : (which == 1) ? g_kpT : g_vpT;

    int tid = threadIdx.x;
    int wid = tid >> 5, lane = tid & 31;
    int wm = wid & 1, wn = wid >> 1;
    int lr = lane >> 2, lk = lane & 3;
    int lg = lane >> 3, li = lane & 7;

    float acc[4][4][4] = {};
    const float* inb = in + ((size_t)b * NC) * NN + n0;
    uint32_t sbB = smem_u32(Bsm);

    // b-frag ldmatrix lane base addresses (per np = pair of n-atoms)
    uint32_t bAddr[2];
#pragma unroll
    for (int np = 0; np < 2; np++) {
        int brow = ((lg & 1) << 3) + li;
        int bcol = wn * 32 + np * 16 + ((lg >> 1) << 3);
        bAddr[np] = sbB + (uint32_t)brow * 272 + (uint32_t)bcol * 2;
    }

    for (int c0 = 0; c0 < NC; c0 += 128) {
        // load W tile [d][c] fp32 -> bf16
#pragma unroll
        for (int i = 0; i < 16; i++) {
            int idx = tid + i * 256;
            int row = idx >> 5, cq = idx & 31;
            float4 w4 = *(const float4*)(Wm + (size_t)row * NC + c0 + cq * 4);
            Asm[row * KW128 + cq * 2]     = pack_bf2(w4.x, w4.y);
            Asm[row * KW128 + cq * 2 + 1] = pack_bf2(w4.z, w4.w);
        }
        // load in tile [c][n] fp32 -> bf16
#pragma unroll
        for (int i = 0; i < 16; i++) {
            int idx = tid + i * 256;
            int row = idx >> 5, nq = idx & 31;
            float4 v4 = *(const float4*)(inb + (size_t)(c0 + row) * NN + nq * 4);
            Bsm[row * KW128 + nq * 2]     = pack_bf2(v4.x, v4.y);
            Bsm[row * KW128 + nq * 2 + 1] = pack_bf2(v4.z, v4.w);
        }
        __syncthreads();

#pragma unroll
        for (int ks = 0; ks < 8; ks++) {
            int k0w = ks * 8;
            uint32_t a[4][4], bb[2][4];
#pragma unroll
            for (int ma = 0; ma < 4; ma++) {
                int w = (wm * 64 + ma * 16 + lr) * KW128 + k0w + lk;
                a[ma][0] = Asm[w];            a[ma][1] = Asm[w + 8 * KW128];
                a[ma][2] = Asm[w + 4];        a[ma][3] = Asm[w + 8 * KW128 + 4];
            }
#pragma unroll
            for (int np = 0; np < 2; np++)
                ldsm4t(bAddr[np] + (uint32_t)ks * 4352, bb[np]);
#pragma unroll
            for (int ma = 0; ma < 4; ma++)
#pragma unroll
                for (int np = 0; np < 2; np++) {
                    mma16816(acc[ma][2 * np],     a[ma][0], a[ma][1], a[ma][2], a[ma][3], bb[np][0], bb[np][1]);
                    mma16816(acc[ma][2 * np + 1], a[ma][0], a[ma][1], a[ma][2], a[ma][3], bb[np][2], bb[np][3]);
                }
        }
        __syncthreads();
    }

    const float s = (which == 0) ? 0.08838834764831845f : 1.0f;
    uint32_t* ob = (uint32_t*)(outp + (size_t)b * ND * NN);   // rows d, cols n (word = 2 n)
#pragma unroll
    for (int ma = 0; ma < 4; ma++) {
        int r0 = wm * 64 + ma * 16 + lr;
#pragma unroll
        for (int na = 0; na < 4; na++) {
            int cw = (n0 >> 1) + wn * 16 + na * 4 + lk;
            ob[(size_t)r0 * (NN / 2) + cw]       = pack_bf2(acc[ma][na][0] * s, acc[ma][na][1] * s);
            ob[(size_t)(r0 + 8) * (NN / 2) + cw] = pack_bf2(acc[ma][na][2] * s, acc[ma][na][3] * s);
        }
    }
}

// ================================================================================
// K2: E[n][m] = exp(qp.kp) with col-sums fused.  A=qpT, B=kpT (both [d][*] K-major,
//   ldmatrix.trans both sides).  grid (32 m, 32 n, NB).
// ================================================================================
__global__ void __launch_bounds__(256, 2) s_kernel()
{
    extern __shared__ uint32_t dsm[];
    uint32_t* Asm = dsm;              // qpT tile [d=128][n=128]
    uint32_t* Bsm = dsm + TILE128;    // kpT tile [d=128][m=128]

    int tid = threadIdx.x;
    int wid = tid >> 5, lane = tid & 31;
    int wm = wid & 1, wn = wid >> 1;
    int lr = lane >> 2, lk = lane & 3;
    int lg = lane >> 3, li = lane & 7;
    int m0 = blockIdx.x * 128, n0 = blockIdx.y * 128, b = blockIdx.z;
    const __nv_bfloat16* qb = g_qpT + (size_t)b * ND * NN;
    const __nv_bfloat16* kb = g_kpT + (size_t)b * ND * NN;

    // load tiles: rows d, 16 uint4 per row
#pragma unroll
    for (int i = 0; i < 8; i++) {
        int idx = tid + i * 256;
        int row = idx >> 4, qx = idx & 15;
        *(uint4*)&Asm[row * KW128 + qx * 4] = *(const uint4*)(qb + (size_t)row * NN + n0 + qx * 8);
        *(uint4*)&Bsm[row * KW128 + qx * 4] = *(const uint4*)(kb + (size_t)row * NN + m0 + qx * 8);
    }
    __syncthreads();

    uint32_t sbA = smem_u32(Asm), sbB = smem_u32(Bsm);
    uint32_t aAddr[4], bAddr[2];
#pragma unroll
    for (int ma = 0; ma < 4; ma++) {
        int arow = ((lg >> 1) << 3) + li;
        int acol = wm * 64 + ma * 16 + ((lg & 1) << 3);
        aAddr[ma] = sbA + (uint32_t)arow * 272 + (uint32_t)acol * 2;
    }
#pragma unroll
    for (int np = 0; np < 2; np++) {
        int brow = ((lg & 1) << 3) + li;
        int bcol = wn * 32 + np * 16 + ((lg >> 1) << 3);
        bAddr[np] = sbB + (uint32_t)brow * 272 + (uint32_t)bcol * 2;
    }

    float acc[4][4][4] = {};
#pragma unroll
    for (int ks = 0; ks < 8; ks++) {
        uint32_t koff = (uint32_t)ks * 4352;
        uint32_t a[4][4], bb[2][4];
#pragma unroll
        for (int ma = 0; ma < 4; ma++) ldsm4t(aAddr[ma] + koff, a[ma]);
#pragma unroll
        for (int np = 0; np < 2; np++) ldsm4t(bAddr[np] + koff, bb[np]);
#pragma unroll
        for (int ma = 0; ma < 4; ma++)
#pragma unroll
            for (int np = 0; np < 2; np++) {
                mma16816(acc[ma][2 * np],     a[ma][0], a[ma][1], a[ma][2], a[ma][3], bb[np][0], bb[np][1]);
                mma16816(acc[ma][2 * np + 1], a[ma][0], a[ma][1], a[ma][2], a[ma][3], bb[np][2], bb[np][3]);
            }
    }
    __syncthreads();

    // epilogue: exp -> stage (stride 68) + fused column partial sums
    uint32_t* stage = Asm;
    float s0[4] = {}, s1[4] = {};
#pragma unroll
    for (int ma = 0; ma < 4; ma++) {
        int r0 = wm * 64 + ma * 16 + lr;
#pragma unroll
        for (int na = 0; na < 4; na++) {
            int cw = wn * 16 + na * 4 + lk;
            float e00 = fexp(acc[ma][na][0]), e01 = fexp(acc[ma][na][1]);
            float e10 = fexp(acc[ma][na][2]), e11 = fexp(acc[ma][na][3]);
            stage[r0 * 68 + cw]       = pack_bf2(e00, e01);
            stage[(r0 + 8) * 68 + cw] = pack_bf2(e10, e11);
            s0[na] += e00 + e10;
            s1[na] += e01 + e11;
        }
    }
#pragma unroll
    for (int na = 0; na < 4; na++) {
#pragma unroll
        for (int off = 4; off < 32; off <<= 1) {
            s0[na] += __shfl_xor_sync(0xffffffffu, s0[na], off);
            s1[na] += __shfl_xor_sync(0xffffffffu, s1[na], off);
        }
    }
    if (lane < 4) {
#pragma unroll
        for (int na = 0; na < 4; na++) {
            int col = m0 + wn * 32 + na * 8 + lane * 2;
            atomicAdd(&g_sum[b * NN + col], s0[na]);
            atomicAdd(&g_sum[b * NN + col + 1], s1[na]);
        }
    }
    __syncthreads();
    uint4* gE4 = (uint4*)g_E;
#pragma unroll
    for (int i = 0; i < 8; i++) {
        int idx = tid + i * 256;
        int row = idx >> 4, qx = idx & 15;
        gE4[((size_t)(b * NN + n0 + row) << 9) + (m0 >> 3) + qx] = *(uint4*)&stage[row * 68 + qx * 4];
    }
}

// ================================================================================
// K3: rinv = 1/sum;  K4: vpT *= rinv[m]  (in place)
// ================================================================================
__global__ void __launch_bounds__(256) rinv_kernel()
{
    int i = blockIdx.x * 256 + threadIdx.x;
    g_rinv[i] = 1.0f / g_sum[i];
}
__global__ void __launch_bounds__(256) vscale_kernel()
{
    int idx = blockIdx.x * 256 + threadIdx.x;          // 1M threads, 4 bf16 each
    int e4 = idx << 2;
    int b = e4 >> 19;                                  // / (ND*NN)
    int m = e4 & (NN - 1);
    uint2 w = *(uint2*)&g_vpT[e4];
    float4 r = *(const float4*)&g_rinv[b * NN + m];
    __nv_bfloat162 p0 = *(__nv_bfloat162*)&w.x;
    __nv_bfloat162 p1 = *(__nv_bfloat162*)&w.y;
    float2 f0 = __bfloat1622float2(p0);
    float2 f1 = __bfloat1622float2(p1);
    uint2 o;
    o.x = pack_bf2(f0.x * r.x, f0.y * r.y);
    o.y = pack_bf2(f1.x * r.z, f1.y * r.w);
    *(uint2*)&g_vpT[e4] = o;
}

// ================================================================================
// K5: avh[n][d] = sum_m E[n][m] * vpT[d][m]   (K=4096, cp.async double-buffered)
// grid (32 n-tiles, NB).
// ================================================================================
__global__ void __launch_bounds__(256, 2) pv_kernel()
{
    extern __shared__ uint32_t dsm[];
    int tid = threadIdx.x;
    int wid = tid >> 5, lane = tid & 31;
    int wm = wid & 1, wn = wid >> 1;
    int lr = lane >> 2, lk = lane & 3;
    int n0 = blockIdx.x * 128, b = blockIdx.y;
    const __nv_bfloat16* Eb = g_E   + (size_t)b * NN * NN;
    const __nv_bfloat16* vt = g_vpT + (size_t)b * ND * NN;
    uint32_t sb = smem_u32(dsm);

    float acc[4][4][4] = {};

    // double buffers: [buf] -> A at buf*2*TILE64, B at +TILE64
    auto issue = [&](int buf, int m0) {
        uint32_t aB = sb + (uint32_t)buf * 2 * TILE64 * 4;
        uint32_t bB = aB + TILE64 * 4;
#pragma unroll
        for (int i = 0; i < 4; i++) {
            int idx = tid + i * 256;
            int row = idx >> 3, qx = idx & 7;
            cpa16(aB + (row * KW64 + qx * 4) * 4, Eb + (size_t)(n0 + row) * NN + m0 + qx * 8);
            cpa16(bB + (row * KW64 + qx * 4) * 4, vt + (size_t)row * NN + m0 + qx * 8);
        }
        CP_COMMIT();
    };

    issue(0, 0);
    for (int it = 0; it < 64; it++) {
        if (it + 1 < 64) {
            issue((it + 1) & 1, (it + 1) * 64);
            CP_WAIT(1);
        } else {
            CP_WAIT(0);
        }
        __syncthreads();
        uint32_t* Asm = dsm + (it & 1) * 2 * TILE64;
        uint32_t* Bsm = Asm + TILE64;
#pragma unroll
        for (int ks = 0; ks < 4; ks++) {
            int k0w = ks * 8;
            uint32_t a[4][4], bb[4][2];
#pragma unroll
            for (int ma = 0; ma < 4; ma++) {
                int w = (wm * 64 + ma * 16 + lr) * KW64 + k0w + lk;
                a[ma][0] = Asm[w];            a[ma][1] = Asm[w + 8 * KW64];
                a[ma][2] = Asm[w + 4];        a[ma][3] = Asm[w + 8 * KW64 + 4];
            }
#pragma unroll
            for (int na = 0; na < 4; na++) {
                int w = (wn * 32 + na * 8 + lr) * KW64 + k0w + lk;
                bb[na][0] = Bsm[w];           bb[na][1] = Bsm[w + 4];
            }
#pragma unroll
            for (int ma = 0; ma < 4; ma++)
#pragma unroll
                for (int na = 0; na < 4; na++)
                    mma16816(acc[ma][na], a[ma][0], a[ma][1], a[ma][2], a[ma][3],
                             bb[na][0], bb[na][1]);
        }
        __syncthreads();
    }

    // epilogue: bf16 [n][d] direct stores
    uint32_t* ob = (uint32_t*)(g_avh + ((size_t)b * NN + n0) * ND);
#pragma unroll
    for (int ma = 0; ma < 4; ma++) {
        int r0 = wm * 64 + ma * 16 + lr;
#pragma unroll
        for (int na = 0; na < 4; na++) {
            int cw = wn * 16 + na * 4 + lk;
            ob[(size_t)r0 * (ND / 2) + cw]       = pack_bf2(acc[ma][na][0], acc[ma][na][1]);
            ob[(size_t)(r0 + 8) * (ND / 2) + cw] = pack_bf2(acc[ma][na][2], acc[ma][na][3]);
        }
    }
}

// ================================================================================
// K6: y[c][n] = v[c][n] + sum_d Wo[c][d] * avh[n][d]   (A=Wo fp32->bf16, B=avh)
// grid (32 n-tiles, 2 c-tiles, NB).
// ================================================================================
__global__ void __launch_bounds__(256, 2) final_kernel(const float* __restrict__ vin,
                                                       const float* __restrict__ Wo,
                                                       float* __restrict__ y)
{
    extern __shared__ uint32_t dsm[];
    uint32_t* Asm = dsm;              // Wo tile [c=128][d=128]
    uint32_t* Bsm = dsm + TILE128;    // avh tile [n=128][d=128]

    int tid = threadIdx.x;
    int wid = tid >> 5, lane = tid & 31;
    int wm = wid & 1, wn = wid >> 1;
    int lr = lane >> 2, lk = lane & 3;
    int n0 = blockIdx.x * 128, c0 = blockIdx.y * 128, b = blockIdx.z;
    const __nv_bfloat16* ab = g_avh + ((size_t)b * NN + n0) * ND;

#pragma unroll
    for (int i = 0; i < 16; i++) {
        int idx = tid + i * 256;
        int row = idx >> 5, dq = idx & 31;
        float4 w4 = *(const float4*)(Wo + (size_t)(c0 + row) * ND + dq * 4);
        Asm[row * KW128 + dq * 2]     = pack_bf2(w4.x, w4.y);
        Asm[row * KW128 + dq * 2 + 1] = pack_bf2(w4.z, w4.w);
    }
#pragma unroll
    for (int i = 0; i < 8; i++) {
        int idx = tid + i * 256;
        int row = idx >> 4, qx = idx & 15;
        *(uint4*)&Bsm[row * KW128 + qx * 4] = *(const uint4*)(ab + (size_t)row * ND + qx * 8);
    }
    __syncthreads();

    float acc[4][4][4] = {};
#pragma unroll
    for (int ks = 0; ks < 8; ks++) {
        int k0w = ks * 8;
        uint32_t a[4][4], bb[4][2];
#pragma unroll
        for (int ma = 0; ma < 4; ma++) {
            int w = (wm * 64 + ma * 16 + lr) * KW128 + k0w + lk;
            a[ma][0] = Asm[w];            a[ma][1] = Asm[w + 8 * KW128];
            a[ma][2] = Asm[w + 4];        a[ma][3] = Asm[w + 8 * KW128 + 4];
        }
#pragma unroll
        for (int na = 0; na < 4; na++) {
            int w = (wn * 32 + na * 8 + lr) * KW128 + k0w + lk;
            bb[na][0] = Bsm[w];           bb[na][1] = Bsm[w + 4];
        }
#pragma unroll
        for (int ma = 0; ma < 4; ma++)
#pragma unroll
            for (int na = 0; na < 4; na++)
                mma16816(acc[ma][na], a[ma][0], a[ma][1], a[ma][2], a[ma][3],
                         bb[na][0], bb[na][1]);
    }

    const float* vb = vin + ((size_t)b * NC + c0) * NN + n0;
    float*       yb = y   + ((size_t)b * NC + c0) * NN + n0;
#pragma unroll
    for (int ma = 0; ma < 4; ma++) {
        int r0 = wm * 64 + ma * 16 + lr;
#pragma unroll
        for (int na = 0; na < 4; na++) {
            int c = wn * 32 + na * 8 + lk * 2;
            float2 v0 = *(const float2*)(vb + (size_t)r0 * NN + c);
            float2 v1 = *(const float2*)(vb + (size_t)(r0 + 8) * NN + c);
            *(float2*)(yb + (size_t)r0 * NN + c)       = make_float2(acc[ma][na][0] + v0.x, acc[ma][na][1] + v0.y);
            *(float2*)(yb + (size_t)(r0 + 8) * NN + c) = make_float2(acc[ma][na][2] + v1.x, acc[ma][na][3] + v1.y);
        }
    }
}

// ================================================================================
extern "C" void kernel_launch(void* const* d_in, const int* in_sizes, int n_in,
                              void* d_out, int out_size)
{
    const float* q  = (const float*)d_in[0];
    const float* k  = (const float*)d_in[1];
    const float* v  = (const float*)d_in[2];
    const float* Wt = (const float*)d_in[3];
    const float* Wp = (const float*)d_in[4];
    const float* Wg = (const float*)d_in[5];
    const float* Wo = (const float*)d_in[6];
    float* y = (float*)d_out;

    static bool attr_done = false;
    if (!attr_done) {
        cudaFuncSetAttribute(proj_kernel,  cudaFuncAttributeMaxDynamicSharedMemorySize, 2 * TILE128 * 4);
        cudaFuncSetAttribute(s_kernel,     cudaFuncAttributeMaxDynamicSharedMemorySize, 2 * TILE128 * 4);
        cudaFuncSetAttribute(pv_kernel,    cudaFuncAttributeMaxDynamicSharedMemorySize, 4 * TILE64 * 4);
        cudaFuncSetAttribute(final_kernel, cudaFuncAttributeMaxDynamicSharedMemorySize, 2 * TILE128 * 4);
        attr_done = true;
    }

    void* sumAddr = nullptr;
    cudaGetSymbolAddress(&sumAddr, g_sum);
    cudaMemsetAsync(sumAddr, 0, NB * NN * sizeof(float));

    proj_kernel  <<<dim3(3, NN / 128, NB), 256, 2 * TILE128 * 4>>>(q, k, v, Wt, Wp, Wg);
    s_kernel     <<<dim3(NN / 128, NN / 128, NB), 256, 2 * TILE128 * 4>>>();
    rinv_kernel  <<<dim3(NB * NN / 256), 256>>>();
    vscale_kernel<<<dim3((NB * ND * NN / 4) / 256), 256>>>();
    pv_kernel    <<<dim3(NN / 128, NB), 256, 4 * TILE64 * 4>>>();
    final_kernel <<<dim3(NN / 128, NC / 128, NB), 256, 2 * TILE128 * 4>>>(v, Wo, y);
}

// round 7
// speedup vs baseline: 11.1366x; 1.0801x over previous
#include <cuda_runtime.h>
#include <cuda_bf16.h>
#include <cstdint>

#define NB 8
#define NC 256
#define ND 128
#define NN 4096   // 64*64

// ---------------- scratch (static device globals; no allocation) ----------------
__device__ __nv_bfloat16 g_qpT[(size_t)NB * ND * NN];     // 8 MB [b][d][n], pre-scaled 1/sqrt(D)
__device__ __nv_bfloat16 g_kpT[(size_t)NB * ND * NN];     // 8 MB [b][d][m]
__device__ __nv_bfloat16 g_vpT[(size_t)NB * ND * NN];     // 8 MB [b][d][m]; later *= 1/sum[m]
__device__ __nv_bfloat16 g_avh[(size_t)NB * NN * ND];     // 8 MB attention out [b][n][d]
__device__ __nv_bfloat16 g_E[(size_t)NB * NN * NN];       // 268 MB E = exp(S) [b][n][m]
__device__ float         g_sum[NB * NN];                  // column sums of E over n

// ---------------- fast exp (FFMA-only) -------------------------------------------
__device__ __forceinline__ float fexp(float x) {
    x = fmaxf(x, -30.0f);
    float t  = fmaf(x, 1.4426950408889634f, 12582912.0f);
    int   i  = __float_as_int(t);
    float fi = t - 12582912.0f;
    float f  = fmaf(x, 1.4426950408889634f, -fi);
    float p  = 9.6181291e-3f;
    p = fmaf(p, f, 5.5504109e-2f);
    p = fmaf(p, f, 2.4022651e-1f);
    p = fmaf(p, f, 6.9314718e-1f);
    p = fmaf(p, f, 1.0f);
    return __int_as_float(__float_as_int(p) + (i << 23));
}
__device__ __forceinline__ uint32_t pack_bf2(float a, float b) {
    __nv_bfloat162 h = __floats2bfloat162_rn(a, b);
    return *reinterpret_cast<uint32_t*>(&h);
}

// ---------------- HMMA + ldmatrix + cp.async helpers -----------------------------
__device__ __forceinline__ void mma16816(float* d,
                                         uint32_t a0, uint32_t a1, uint32_t a2, uint32_t a3,
                                         uint32_t b0, uint32_t b1) {
    asm volatile(
        "mma.sync.aligned.m16n8k16.row.col.f32.bf16.bf16.f32 "
        "{%0,%1,%2,%3}, {%4,%5,%6,%7}, {%8,%9}, {%0,%1,%2,%3};"
        : "+f"(d[0]), "+f"(d[1]), "+f"(d[2]), "+f"(d[3])
        : "r"(a0), "r"(a1), "r"(a2), "r"(a3), "r"(b0), "r"(b1));
}
__device__ __forceinline__ void ldsm4t(uint32_t addr, uint32_t* r) {
    asm volatile("ldmatrix.sync.aligned.m8n8.x4.trans.shared.b16 {%0,%1,%2,%3}, [%4];"
                 : "=r"(r[0]), "=r"(r[1]), "=r"(r[2]), "=r"(r[3]) : "r"(addr));
}
__device__ __forceinline__ void ldsm4(uint32_t addr, uint32_t* r) {
    asm volatile("ldmatrix.sync.aligned.m8n8.x4.shared.b16 {%0,%1,%2,%3}, [%4];"
                 : "=r"(r[0]), "=r"(r[1]), "=r"(r[2]), "=r"(r[3]) : "r"(addr));
}
__device__ __forceinline__ void cpa16(uint32_t dst, const void* src) {
    asm volatile("cp.async.cg.shared.global [%0], [%1], 16;" :: "r"(dst), "l"(src) : "memory");
}
#define CP_COMMIT() asm volatile("cp.async.commit_group;" ::: "memory")
#define CP_WAIT(n)  asm volatile("cp.async.wait_group %0;" :: "n"(n) : "memory")
__device__ __forceinline__ uint32_t smem_u32(const void* p) {
    return (uint32_t)__cvta_generic_to_shared(p);
}

// smem row strides (words): 128 bf16 + 8 pad = 68 words (bank shift 4 per row)
#define KW128 68
#define TILE128 (128 * KW128)     // 8704 words = 34816 B
// 64-col chunk rows: 32 + 4 pad = 36 words
#define KW64 36
#define TILE64 (128 * KW64)       // 4608 words = 18432 B

// ================================================================================
// K1: projections -> TRANSPOSED outputs [d][n].  (unchanged from R5)
// ================================================================================
__global__ void __launch_bounds__(256, 2) proj_kernel(
    const float* __restrict__ q, const float* __restrict__ k, const float* __restrict__ v,
    const float* __restrict__ Wt, const float* __restrict__ Wp, const float* __restrict__ Wg)
{
    extern __shared__ uint32_t dsm[];
    uint32_t* Asm = dsm;              // W tile  [d=128][c=128]
    uint32_t* Bsm = dsm + TILE128;    // in tile [c=128][n=128]

    int which = blockIdx.x;
    int n0    = blockIdx.y * 128;
    int b     = blockIdx.z;
    const float* in = (which == 0) ? q  : (which == 1) ? k  : v;
    const float* Wm = (which == 0) ? Wt : (which == 1) ? Wp : Wg;
    __nv_bfloat16* outp = (which == 0) ? g_qpT : (which == 1) ? g_kpT : g_vpT;

    int tid = threadIdx.x;
    int wid = tid >> 5, lane = tid & 31;
    int wm = wid & 1, wn = wid >> 1;
    int lr = lane >> 2, lk = lane & 3;
    int lg = lane >> 3, li = lane & 7;

    float acc[4][4][4] = {};
    const float* inb = in + ((size_t)b * NC) * NN + n0;
    uint32_t sbB = smem_u32(Bsm);

    uint32_t bAddr[2];
#pragma unroll
    for (int np = 0; np < 2; np++) {
        int brow = ((lg & 1) << 3) + li;
        int bcol = wn * 32 + np * 16 + ((lg >> 1) << 3);
        bAddr[np] = sbB + (uint32_t)brow * 272 + (uint32_t)bcol * 2;
    }

    for (int c0 = 0; c0 < NC; c0 += 128) {
#pragma unroll
        for (int i = 0; i < 16; i++) {
            int idx = tid + i * 256;
            int row = idx >> 5, cq = idx & 31;
            float4 w4 = *(const float4*)(Wm + (size_t)row * NC + c0 + cq * 4);
            Asm[row * KW128 + cq * 2]     = pack_bf2(w4.x, w4.y);
            Asm[row * KW128 + cq * 2 + 1] = pack_bf2(w4.z, w4.w);
        }
#pragma unroll
        for (int i = 0; i < 16; i++) {
            int idx = tid + i * 256;
            int row = idx >> 5, nq = idx & 31;
            float4 v4 = *(const float4*)(inb + (size_t)(c0 + row) * NN + nq * 4);
            Bsm[row * KW128 + nq * 2]     = pack_bf2(v4.x, v4.y);
            Bsm[row * KW128 + nq * 2 + 1] = pack_bf2(v4.z, v4.w);
        }
        __syncthreads();

#pragma unroll
        for (int ks = 0; ks < 8; ks++) {
            int k0w = ks * 8;
            uint32_t a[4][4], bb[2][4];
#pragma unroll
            for (int ma = 0; ma < 4; ma++) {
                int w = (wm * 64 + ma * 16 + lr) * KW128 + k0w + lk;
                a[ma][0] = Asm[w];            a[ma][1] = Asm[w + 8 * KW128];
                a[ma][2] = Asm[w + 4];        a[ma][3] = Asm[w + 8 * KW128 + 4];
            }
#pragma unroll
            for (int np = 0; np < 2; np++)
                ldsm4t(bAddr[np] + (uint32_t)ks * 4352, bb[np]);
#pragma unroll
            for (int ma = 0; ma < 4; ma++)
#pragma unroll
                for (int np = 0; np < 2; np++) {
                    mma16816(acc[ma][2 * np],     a[ma][0], a[ma][1], a[ma][2], a[ma][3], bb[np][0], bb[np][1]);
                    mma16816(acc[ma][2 * np + 1], a[ma][0], a[ma][1], a[ma][2], a[ma][3], bb[np][2], bb[np][3]);
                }
        }
        __syncthreads();
    }

    const float s = (which == 0) ? 0.08838834764831845f : 1.0f;
    uint32_t* ob = (uint32_t*)(outp + (size_t)b * ND * NN);
#pragma unroll
    for (int ma = 0; ma < 4; ma++) {
        int r0 = wm * 64 + ma * 16 + lr;
#pragma unroll
        for (int na = 0; na < 4; na++) {
            int cw = (n0 >> 1) + wn * 16 + na * 4 + lk;
            ob[(size_t)r0 * (NN / 2) + cw]       = pack_bf2(acc[ma][na][0] * s, acc[ma][na][1] * s);
            ob[(size_t)(r0 + 8) * (NN / 2) + cw] = pack_bf2(acc[ma][na][2] * s, acc[ma][na][3] * s);
        }
    }
}

// ================================================================================
// K2 (persistent): one block per (n-tile, b); qp tile resident, kp chunks streamed
// via cp.async; E chunks written through retiring-buffer smem stage; col-sums fused.
// smem words: Q [0,8704), K0 [8704,17408), K1 [17408,26112)  = 104448 B
// ================================================================================
__global__ void __launch_bounds__(256, 2) s_kernel()
{
    extern __shared__ uint32_t dsm[];
    int tid = threadIdx.x;
    int wid = tid >> 5, lane = tid & 31;
    int wm = wid & 1, wn = wid >> 1;
    int lr = lane >> 2, lk = lane & 3;
    int lg = lane >> 3, li = lane & 7;
    int n0 = blockIdx.x * 128, b = blockIdx.y;
    const __nv_bfloat16* qb = g_qpT + (size_t)b * ND * NN;
    const __nv_bfloat16* kb = g_kpT + (size_t)b * ND * NN;
    uint32_t sb = smem_u32(dsm);

    // issue Q tile + kp chunk 0 as one cp.async group
#pragma unroll
    for (int i = 0; i < 8; i++) {
        int idx = tid + i * 256;
        int row = idx >> 4, qx = idx & 15;
        cpa16(sb + (uint32_t)(row * KW128 + qx * 4) * 4,         qb + (size_t)row * NN + n0 + qx * 8);
        cpa16(sb + 34816u + (uint32_t)(row * KW128 + qx * 4) * 4, kb + (size_t)row * NN + qx * 8);
    }
    CP_COMMIT();

    // fragment lane addresses
    uint32_t aAddr[4], bBase[2];
#pragma unroll
    for (int ma = 0; ma < 4; ma++) {
        int arow = ((lg >> 1) << 3) + li;
        int acol = wm * 64 + ma * 16 + ((lg & 1) << 3);
        aAddr[ma] = sb + (uint32_t)arow * 272 + (uint32_t)acol * 2;
    }
#pragma unroll
    for (int np = 0; np < 2; np++) {
        int brow = ((lg & 1) << 3) + li;
        int bcol = wn * 32 + np * 16 + ((lg >> 1) << 3);
        bBase[np] = sb + (uint32_t)brow * 272 + (uint32_t)bcol * 2;
    }

    uint4* gE4 = (uint4*)g_E;

    for (int mc = 0; mc < 32; mc++) {
        int buf = mc & 1;
        if (mc + 1 < 32) {
            uint32_t kB = sb + 34816u + (uint32_t)((mc + 1) & 1) * 34816u;
            const __nv_bfloat16* ks = kb + (mc + 1) * 128;
#pragma unroll
            for (int i = 0; i < 8; i++) {
                int idx = tid + i * 256;
                int row = idx >> 4, qx = idx & 15;
                cpa16(kB + (uint32_t)(row * KW128 + qx * 4) * 4, ks + (size_t)row * NN + qx * 8);
            }
            CP_COMMIT();
            CP_WAIT(1);
        } else {
            CP_WAIT(0);
        }
        __syncthreads();

        uint32_t bOff = 34816u + (uint32_t)buf * 34816u;
        float acc[4][4][4] = {};
#pragma unroll
        for (int ks = 0; ks < 8; ks++) {
            uint32_t koff = (uint32_t)ks * 4352;
            uint32_t a[4][4], bb[2][4];
#pragma unroll
            for (int ma = 0; ma < 4; ma++) ldsm4t(aAddr[ma] + koff, a[ma]);
#pragma unroll
            for (int np = 0; np < 2; np++) ldsm4t(bBase[np] + bOff + koff, bb[np]);
#pragma unroll
            for (int ma = 0; ma < 4; ma++)
#pragma unroll
                for (int np = 0; np < 2; np++) {
                    mma16816(acc[ma][2 * np],     a[ma][0], a[ma][1], a[ma][2], a[ma][3], bb[np][0], bb[np][1]);
                    mma16816(acc[ma][2 * np + 1], a[ma][0], a[ma][1], a[ma][2], a[ma][3], bb[np][2], bb[np][3]);
                }
        }
        __syncthreads();   // all warps done reading kp chunk -> buffer reusable as stage

        // epilogue: exp -> stage into retiring buffer + fused col sums
        uint32_t* stage = dsm + 8704 + buf * 8704;
        float s0[4] = {}, s1[4] = {};
#pragma unroll
        for (int ma = 0; ma < 4; ma++) {
            int r0 = wm * 64 + ma * 16 + lr;
#pragma unroll
            for (int na = 0; na < 4; na++) {
                int cw = wn * 16 + na * 4 + lk;
                float e00 = fexp(acc[ma][na][0]), e01 = fexp(acc[ma][na][1]);
                float e10 = fexp(acc[ma][na][2]), e11 = fexp(acc[ma][na][3]);
                stage[r0 * 68 + cw]       = pack_bf2(e00, e01);
                stage[(r0 + 8) * 68 + cw] = pack_bf2(e10, e11);
                s0[na] += e00 + e10;
                s1[na] += e01 + e11;
            }
        }
#pragma unroll
        for (int na = 0; na < 4; na++) {
#pragma unroll
            for (int off = 4; off < 32; off <<= 1) {
                s0[na] += __shfl_xor_sync(0xffffffffu, s0[na], off);
                s1[na] += __shfl_xor_sync(0xffffffffu, s1[na], off);
            }
        }
        if (lane < 4) {
#pragma unroll
            for (int na = 0; na < 4; na++) {
                int col = mc * 128 + wn * 32 + na * 8 + lane * 2;
                atomicAdd(&g_sum[b * NN + col], s0[na]);
                atomicAdd(&g_sum[b * NN + col + 1], s1[na]);
            }
        }
        __syncthreads();   // stage complete

        size_t ebase = ((size_t)(b * NN + n0)) << 9;
        int mq = mc * 16;
#pragma unroll
        for (int i = 0; i < 8; i++) {
            int idx = tid + i * 256;
            int row = idx >> 4, qx = idx & 15;
            gE4[ebase + ((size_t)row << 9) + mq + qx] = *(uint4*)&stage[row * 68 + qx * 4];
        }
        __syncthreads();   // stage reads done; next iter's cp.async may overwrite
    }
}

// ================================================================================
// K3: vpT[b,d,m] *= 1/sum[b,m]   (rinv fused)
// ================================================================================
__global__ void __launch_bounds__(256) vscale_kernel()
{
    int idx = blockIdx.x * 256 + threadIdx.x;          // 1M threads, 4 bf16 each
    int e4 = idx << 2;
    int b = e4 >> 19;                                  // / (ND*NN)
    int m = e4 & (NN - 1);
    uint2 w = *(uint2*)&g_vpT[e4];
    float4 s4 = *(const float4*)&g_sum[b * NN + m];
    __nv_bfloat162 p0 = *(__nv_bfloat162*)&w.x;
    __nv_bfloat162 p1 = *(__nv_bfloat162*)&w.y;
    float2 f0 = __bfloat1622float2(p0);
    float2 f1 = __bfloat1622float2(p1);
    uint2 o;
    o.x = pack_bf2(f0.x / s4.x, f0.y / s4.y);
    o.y = pack_bf2(f1.x / s4.z, f1.y / s4.w);
    *(uint2*)&g_vpT[e4] = o;
}

// ================================================================================
// K4: avh[n][d] = sum_m E[n][m] * vpT[d][m]   (K=4096, 3-stage cp.async, ldmatrix)
// smem: 3 stages x (A 18432 + B 18432) = 110592 B
// ================================================================================
__global__ void __launch_bounds__(256, 2) pv_kernel()
{
    extern __shared__ uint32_t dsm[];
    int tid = threadIdx.x;
    int wid = tid >> 5, lane = tid & 31;
    int wm = wid & 1, wn = wid >> 1;
    int lr = lane >> 2, lk = lane & 3;
    int lg = lane >> 3, li = lane & 7;
    int n0 = blockIdx.x * 128, b = blockIdx.y;
    const __nv_bfloat16* Eb = g_E   + (size_t)b * NN * NN;
    const __nv_bfloat16* vt = g_vpT + (size_t)b * ND * NN;
    uint32_t sb = smem_u32(dsm);

    float acc[4][4][4] = {};

    // ldmatrix lane base offsets (bytes, within a stage)
    uint32_t aBase[4], bBase[2];
#pragma unroll
    for (int ma = 0; ma < 4; ma++)
        aBase[ma] = (uint32_t)(wm * 64 + ma * 16 + ((lg & 1) << 3) + li) * (KW64 * 4) + ((lg >> 1) << 4);
#pragma unroll
    for (int np = 0; np < 2; np++)
        bBase[np] = 18432u + (uint32_t)(wn * 32 + np * 16 + ((lg >> 1) << 3) + li) * (KW64 * 4) + ((lg & 1) << 4);

    auto issue = [&](int stg, int m0) {
        uint32_t aB = sb + (uint32_t)stg * 36864u;
        uint32_t bB = aB + 18432u;
#pragma unroll
        for (int i = 0; i < 4; i++) {
            int idx = tid + i * 256;
            int row = idx >> 3, qx = idx & 7;
            cpa16(aB + (uint32_t)(row * KW64 + qx * 4) * 4, Eb + (size_t)(n0 + row) * NN + m0 + qx * 8);
            cpa16(bB + (uint32_t)(row * KW64 + qx * 4) * 4, vt + (size_t)row * NN + m0 + qx * 8);
        }
        CP_COMMIT();
    };

    issue(0, 0);
    issue(1, 64);
    int stg = 0;
    for (int it = 0; it < 64; it++) {
        if (it + 2 < 64) {
            issue((it + 2) % 3, (it + 2) * 64);
            CP_WAIT(2);
        } else {
            CP_WAIT(0);
        }
        __syncthreads();
        uint32_t sOff = sb + (uint32_t)stg * 36864u;
#pragma unroll
        for (int ks = 0; ks < 4; ks++) {
            uint32_t koff = (uint32_t)ks * 32;
            uint32_t a[4][4], bb[2][4];
#pragma unroll
            for (int ma = 0; ma < 4; ma++) ldsm4(sOff + aBase[ma] + koff, a[ma]);
#pragma unroll
            for (int np = 0; np < 2; np++) ldsm4(sOff + bBase[np] + koff, bb[np]);
#pragma unroll
            for (int ma = 0; ma < 4; ma++)
#pragma unroll
                for (int np = 0; np < 2; np++) {
                    mma16816(acc[ma][2 * np],     a[ma][0], a[ma][1], a[ma][2], a[ma][3], bb[np][0], bb[np][1]);
                    mma16816(acc[ma][2 * np + 1], a[ma][0], a[ma][1], a[ma][2], a[ma][3], bb[np][2], bb[np][3]);
                }
        }
        __syncthreads();
        stg = (stg + 1) % 3;
    }

    // epilogue: bf16 [n][d] direct stores
    uint32_t* ob = (uint32_t*)(g_avh + ((size_t)b * NN + n0) * ND);
#pragma unroll
    for (int ma = 0; ma < 4; ma++) {
        int r0 = wm * 64 + ma * 16 + lr;
#pragma unroll
        for (int na = 0; na < 4; na++) {
            int cw = wn * 16 + na * 4 + lk;
            ob[(size_t)r0 * (ND / 2) + cw]       = pack_bf2(acc[ma][na][0], acc[ma][na][1]);
            ob[(size_t)(r0 + 8) * (ND / 2) + cw] = pack_bf2(acc[ma][na][2], acc[ma][na][3]);
        }
    }
}

// ================================================================================
// K5: y[c][n] = v[c][n] + sum_d Wo[c][d] * avh[n][d]   (unchanged)
// ================================================================================
__global__ void __launch_bounds__(256, 2) final_kernel(const float* __restrict__ vin,
                                                       const float* __restrict__ Wo,
                                                       float* __restrict__ y)
{
    extern __shared__ uint32_t dsm[];
    uint32_t* Asm = dsm;              // Wo tile [c=128][d=128]
    uint32_t* Bsm = dsm + TILE128;    // avh tile [n=128][d=128]

    int tid = threadIdx.x;
    int wid = tid >> 5, lane = tid & 31;
    int wm = wid & 1, wn = wid >> 1;
    int lr = lane >> 2, lk = lane & 3;
    int n0 = blockIdx.x * 128, c0 = blockIdx.y * 128, b = blockIdx.z;
    const __nv_bfloat16* ab = g_avh + ((size_t)b * NN + n0) * ND;

#pragma unroll
    for (int i = 0; i < 16; i++) {
        int idx = tid + i * 256;
        int row = idx >> 5, dq = idx & 31;
        float4 w4 = *(const float4*)(Wo + (size_t)(c0 + row) * ND + dq * 4);
        Asm[row * KW128 + dq * 2]     = pack_bf2(w4.x, w4.y);
        Asm[row * KW128 + dq * 2 + 1] = pack_bf2(w4.z, w4.w);
    }
#pragma unroll
    for (int i = 0; i < 8; i++) {
        int idx = tid + i * 256;
        int row = idx >> 4, qx = idx & 15;
        *(uint4*)&Bsm[row * KW128 + qx * 4] = *(const uint4*)(ab + (size_t)row * ND + qx * 8);
    }
    __syncthreads();

    float acc[4][4][4] = {};
#pragma unroll
    for (int ks = 0; ks < 8; ks++) {
        int k0w = ks * 8;
        uint32_t a[4][4], bb[4][2];
#pragma unroll
        for (int ma = 0; ma < 4; ma++) {
            int w = (wm * 64 + ma * 16 + lr) * KW128 + k0w + lk;
            a[ma][0] = Asm[w];            a[ma][1] = Asm[w + 8 * KW128];
            a[ma][2] = Asm[w + 4];        a[ma][3] = Asm[w + 8 * KW128 + 4];
        }
#pragma unroll
        for (int na = 0; na < 4; na++) {
            int w = (wn * 32 + na * 8 + lr) * KW128 + k0w + lk;
            bb[na][0] = Bsm[w];           bb[na][1] = Bsm[w + 4];
        }
#pragma unroll
        for (int ma = 0; ma < 4; ma++)
#pragma unroll
            for (int na = 0; na < 4; na++)
                mma16816(acc[ma][na], a[ma][0], a[ma][1], a[ma][2], a[ma][3],
                         bb[na][0], bb[na][1]);
    }

    const float* vb = vin + ((size_t)b * NC + c0) * NN + n0;
    float*       yb = y   + ((size_t)b * NC + c0) * NN + n0;
#pragma unroll
    for (int ma = 0; ma < 4; ma++) {
        int r0 = wm * 64 + ma * 16 + lr;
#pragma unroll
        for (int na = 0; na < 4; na++) {
            int c = wn * 32 + na * 8 + lk * 2;
            float2 v0 = *(const float2*)(vb + (size_t)r0 * NN + c);
            float2 v1 = *(const float2*)(vb + (size_t)(r0 + 8) * NN + c);
            *(float2*)(yb + (size_t)r0 * NN + c)       = make_float2(acc[ma][na][0] + v0.x, acc[ma][na][1] + v0.y);
            *(float2*)(yb + (size_t)(r0 + 8) * NN + c) = make_float2(acc[ma][na][2] + v1.x, acc[ma][na][3] + v1.y);
        }
    }
}

// ================================================================================
extern "C" void kernel_launch(void* const* d_in, const int* in_sizes, int n_in,
                              void* d_out, int out_size)
{
    const float* q  = (const float*)d_in[0];
    const float* k  = (const float*)d_in[1];
    const float* v  = (const float*)d_in[2];
    const float* Wt = (const float*)d_in[3];
    const float* Wp = (const float*)d_in[4];
    const float* Wg = (const float*)d_in[5];
    const float* Wo = (const float*)d_in[6];
    float* y = (float*)d_out;

    cudaFuncSetAttribute(proj_kernel,  cudaFuncAttributeMaxDynamicSharedMemorySize, 2 * TILE128 * 4);
    cudaFuncSetAttribute(s_kernel,     cudaFuncAttributeMaxDynamicSharedMemorySize, 3 * TILE128 * 4);
    cudaFuncSetAttribute(pv_kernel,    cudaFuncAttributeMaxDynamicSharedMemorySize, 6 * TILE64 * 4);
    cudaFuncSetAttribute(final_kernel, cudaFuncAttributeMaxDynamicSharedMemorySize, 2 * TILE128 * 4);

    void* sumAddr = nullptr;
    cudaGetSymbolAddress(&sumAddr, g_sum);
    cudaMemsetAsync(sumAddr, 0, NB * NN * sizeof(float));

    proj_kernel  <<<dim3(3, NN / 128, NB), 256, 2 * TILE128 * 4>>>(q, k, v, Wt, Wp, Wg);
    s_kernel     <<<dim3(NN / 128, NB), 256, 3 * TILE128 * 4>>>();
    vscale_kernel<<<dim3((NB * ND * NN / 4) / 256), 256>>>();
    pv_kernel    <<<dim3(NN / 128, NB), 256, 6 * TILE64 * 4>>>();
    final_kernel <<<dim3(NN / 128, NC / 128, NB), 256, 2 * TILE128 * 4>>>(v, Wo, y);
}

// round 8
// speedup vs baseline: 11.2260x; 1.0080x over previous
#include <cuda_runtime.h>
#include <cuda_bf16.h>
#include <cstdint>

#define NB 8
#define NC 256
#define ND 128
#define NN 4096   // 64*64

// ---------------- scratch (static device globals; no allocation) ----------------
__device__ __nv_bfloat16 g_qpT[(size_t)NB * ND * NN];     // 8 MB [b][d][n], pre-scaled 1/sqrt(D)
__device__ __nv_bfloat16 g_kpT[(size_t)NB * ND * NN];     // 8 MB [b][d][m]
__device__ __nv_bfloat16 g_vpT[(size_t)NB * ND * NN];     // 8 MB [b][d][m]; later *= 1/sum[m]
__device__ __nv_bfloat16 g_avh[(size_t)NB * NN * ND];     // 8 MB attention out [b][n][d]
__device__ __nv_bfloat16 g_E[(size_t)NB * NN * NN];       // 268 MB E = exp(S) [b][n][m]
__device__ float         g_sum[NB * NN];                  // column sums of E over n

// ---------------- fast exp (FFMA-only) -------------------------------------------
__device__ __forceinline__ float fexp(float x) {
    x = fmaxf(x, -30.0f);
    float t  = fmaf(x, 1.4426950408889634f, 12582912.0f);
    int   i  = __float_as_int(t);
    float fi = t - 12582912.0f;
    float f  = fmaf(x, 1.4426950408889634f, -fi);
    float p  = 9.6181291e-3f;
    p = fmaf(p, f, 5.5504109e-2f);
    p = fmaf(p, f, 2.4022651e-1f);
    p = fmaf(p, f, 6.9314718e-1f);
    p = fmaf(p, f, 1.0f);
    return __int_as_float(__float_as_int(p) + (i << 23));
}
__device__ __forceinline__ uint32_t pack_bf2(float a, float b) {
    __nv_bfloat162 h = __floats2bfloat162_rn(a, b);
    return *reinterpret_cast<uint32_t*>(&h);
}

// ---------------- HMMA + ldmatrix + cp.async helpers -----------------------------
__device__ __forceinline__ void mma16816(float* d,
                                         uint32_t a0, uint32_t a1, uint32_t a2, uint32_t a3,
                                         uint32_t b0, uint32_t b1) {
    asm volatile(
        "mma.sync.aligned.m16n8k16.row.col.f32.bf16.bf16.f32 "
        "{%0,%1,%2,%3}, {%4,%5,%6,%7}, {%8,%9}, {%0,%1,%2,%3};"
        : "+f"(d[0]), "+f"(d[1]), "+f"(d[2]), "+f"(d[3])
        : "r"(a0), "r"(a1), "r"(a2), "r"(a3), "r"(b0), "r"(b1));
}
__device__ __forceinline__ void ldsm4t(uint32_t addr, uint32_t* r) {
    asm volatile("ldmatrix.sync.aligned.m8n8.x4.trans.shared.b16 {%0,%1,%2,%3}, [%4];"
                 : "=r"(r[0]), "=r"(r[1]), "=r"(r[2]), "=r"(r[3]) : "r"(addr));
}
__device__ __forceinline__ void ldsm4(uint32_t addr, uint32_t* r) {
    asm volatile("ldmatrix.sync.aligned.m8n8.x4.shared.b16 {%0,%1,%2,%3}, [%4];"
                 : "=r"(r[0]), "=r"(r[1]), "=r"(r[2]), "=r"(r[3]) : "r"(addr));
}
__device__ __forceinline__ void cpa16(uint32_t dst, const void* src) {
    asm volatile("cp.async.cg.shared.global [%0], [%1], 16;" :: "r"(dst), "l"(src) : "memory");
}
#define CP_COMMIT() asm volatile("cp.async.commit_group;" ::: "memory")
#define CP_WAIT(n)  asm volatile("cp.async.wait_group %0;" :: "n"(n) : "memory")
__device__ __forceinline__ uint32_t smem_u32(const void* p) {
    return (uint32_t)__cvta_generic_to_shared(p);
}

// smem row strides (words): 128 bf16 + 8 pad = 68 words (bank shift 4 per row)
#define KW128 68
#define TILE128 (128 * KW128)     // 8704 words = 34816 B
// 64-col chunk rows: 32 + 4 pad = 36 words
#define KW64 36
#define TILE64 (128 * KW64)       // 4608 words = 18432 B

// ================================================================================
// K1: projections -> TRANSPOSED outputs [d][n].  (unchanged)
// ================================================================================
__global__ void __launch_bounds__(256, 2) proj_kernel(
    const float* __restrict__ q, const float* __restrict__ k, const float* __restrict__ v,
    const float* __restrict__ Wt, const float* __restrict__ Wp, const float* __restrict__ Wg)
{
    extern __shared__ uint32_t dsm[];
    uint32_t* Asm = dsm;              // W tile  [d=128][c=128]
    uint32_t* Bsm = dsm + TILE128;    // in tile [c=128][n=128]

    int which = blockIdx.x;
    int n0    = blockIdx.y * 128;
    int b     = blockIdx.z;
    const float* in = (which == 0) ? q  : (which == 1) ? k  : v;
    const float* Wm = (which == 0) ? Wt : (which == 1) ? Wp : Wg;
    __nv_bfloat16* outp = (which == 0) ? g_qpT : (which == 1) ? g_kpT : g_vpT;

    int tid = threadIdx.x;
    int wid = tid >> 5, lane = tid & 31;
    int wm = wid & 1, wn = wid >> 1;
    int lr = lane >> 2, lk = lane & 3;
    int lg = lane >> 3, li = lane & 7;

    float acc[4][4][4] = {};
    const float* inb = in + ((size_t)b * NC) * NN + n0;
    uint32_t sbB = smem_u32(Bsm);

    uint32_t bAddr[2];
#pragma unroll
    for (int np = 0; np < 2; np++) {
        int brow = ((lg & 1) << 3) + li;
        int bcol = wn * 32 + np * 16 + ((lg >> 1) << 3);
        bAddr[np] = sbB + (uint32_t)brow * 272 + (uint32_t)bcol * 2;
    }

    for (int c0 = 0; c0 < NC; c0 += 128) {
#pragma unroll
        for (int i = 0; i < 16; i++) {
            int idx = tid + i * 256;
            int row = idx >> 5, cq = idx & 31;
            float4 w4 = *(const float4*)(Wm + (size_t)row * NC + c0 + cq * 4);
            Asm[row * KW128 + cq * 2]     = pack_bf2(w4.x, w4.y);
            Asm[row * KW128 + cq * 2 + 1] = pack_bf2(w4.z, w4.w);
        }
#pragma unroll
        for (int i = 0; i < 16; i++) {
            int idx = tid + i * 256;
            int row = idx >> 5, nq = idx & 31;
            float4 v4 = *(const float4*)(inb + (size_t)(c0 + row) * NN + nq * 4);
            Bsm[row * KW128 + nq * 2]     = pack_bf2(v4.x, v4.y);
            Bsm[row * KW128 + nq * 2 + 1] = pack_bf2(v4.z, v4.w);
        }
        __syncthreads();

#pragma unroll
        for (int ks = 0; ks < 8; ks++) {
            int k0w = ks * 8;
            uint32_t a[4][4], bb[2][4];
#pragma unroll
            for (int ma = 0; ma < 4; ma++) {
                int w = (wm * 64 + ma * 16 + lr) * KW128 + k0w + lk;
                a[ma][0] = Asm[w];            a[ma][1] = Asm[w + 8 * KW128];
                a[ma][2] = Asm[w + 4];        a[ma][3] = Asm[w + 8 * KW128 + 4];
            }
#pragma unroll
            for (int np = 0; np < 2; np++)
                ldsm4t(bAddr[np] + (uint32_t)ks * 4352, bb[np]);
#pragma unroll
            for (int ma = 0; ma < 4; ma++)
#pragma unroll
                for (int np = 0; np < 2; np++) {
                    mma16816(acc[ma][2 * np],     a[ma][0], a[ma][1], a[ma][2], a[ma][3], bb[np][0], bb[np][1]);
                    mma16816(acc[ma][2 * np + 1], a[ma][0], a[ma][1], a[ma][2], a[ma][3], bb[np][2], bb[np][3]);
                }
        }
        __syncthreads();
    }

    const float s = (which == 0) ? 0.08838834764831845f : 1.0f;
    uint32_t* ob = (uint32_t*)(outp + (size_t)b * ND * NN);
#pragma unroll
    for (int ma = 0; ma < 4; ma++) {
        int r0 = wm * 64 + ma * 16 + lr;
#pragma unroll
        for (int na = 0; na < 4; na++) {
            int cw = (n0 >> 1) + wn * 16 + na * 4 + lk;
            ob[(size_t)r0 * (NN / 2) + cw]       = pack_bf2(acc[ma][na][0] * s, acc[ma][na][1] * s);
            ob[(size_t)(r0 + 8) * (NN / 2) + cw] = pack_bf2(acc[ma][na][2] * s, acc[ma][na][3] * s);
        }
    }
}

// ================================================================================
// K2 (persistent): qp tile resident; kp chunks streamed with prefetch issued right
// after the top barrier (overlaps mma+epilogue+store); 3 barriers per chunk.
// smem words: Q [0,8704), K0 [8704,17408), K1 [17408,26112)  = 104448 B
// ================================================================================
__global__ void __launch_bounds__(256, 2) s_kernel()
{
    extern __shared__ uint32_t dsm[];
    int tid = threadIdx.x;
    int wid = tid >> 5, lane = tid & 31;
    int wm = wid & 1, wn = wid >> 1;
    int lr = lane >> 2, lk = lane & 3;
    int lg = lane >> 3, li = lane & 7;
    int n0 = blockIdx.x * 128, b = blockIdx.y;
    const __nv_bfloat16* qb = g_qpT + (size_t)b * ND * NN;
    const __nv_bfloat16* kb = g_kpT + (size_t)b * ND * NN;
    uint32_t sb = smem_u32(dsm);

    // issue Q tile + kp chunk 0 as one cp.async group
#pragma unroll
    for (int i = 0; i < 8; i++) {
        int idx = tid + i * 256;
        int row = idx >> 4, qx = idx & 15;
        cpa16(sb + (uint32_t)(row * KW128 + qx * 4) * 4,          qb + (size_t)row * NN + n0 + qx * 8);
        cpa16(sb + 34816u + (uint32_t)(row * KW128 + qx * 4) * 4, kb + (size_t)row * NN + qx * 8);
    }
    CP_COMMIT();

    // fragment lane addresses
    uint32_t aAddr[4], bBase[2];
#pragma unroll
    for (int ma = 0; ma < 4; ma++) {
        int arow = ((lg >> 1) << 3) + li;
        int acol = wm * 64 + ma * 16 + ((lg & 1) << 3);
        aAddr[ma] = sb + (uint32_t)arow * 272 + (uint32_t)acol * 2;
    }
#pragma unroll
    for (int np = 0; np < 2; np++) {
        int brow = ((lg & 1) << 3) + li;
        int bcol = wn * 32 + np * 16 + ((lg >> 1) << 3);
        bBase[np] = sb + (uint32_t)brow * 272 + (uint32_t)bcol * 2;
    }

    uint4* gE4 = (uint4*)g_E;

    for (int mc = 0; mc < 32; mc++) {
        int buf = mc & 1;
        CP_WAIT(0);
        __syncthreads();          // kp(mc) visible; stage reads of chunk mc-1 all done

        // prefetch kp(mc+1) into the buffer just freed (overlaps everything below)
        if (mc + 1 < 32) {
            uint32_t kB = sb + 34816u + (uint32_t)((mc + 1) & 1) * 34816u;
            const __nv_bfloat16* ksrc = kb + (mc + 1) * 128;
#pragma unroll
            for (int i = 0; i < 8; i++) {
                int idx = tid + i * 256;
                int row = idx >> 4, qx = idx & 15;
                cpa16(kB + (uint32_t)(row * KW128 + qx * 4) * 4, ksrc + (size_t)row * NN + qx * 8);
            }
            CP_COMMIT();
        }

        uint32_t bOff = 34816u + (uint32_t)buf * 34816u;
        float acc[4][4][4] = {};
#pragma unroll
        for (int ks = 0; ks < 8; ks++) {
            uint32_t koff = (uint32_t)ks * 4352;
            uint32_t a[4][4], bb[2][4];
#pragma unroll
            for (int ma = 0; ma < 4; ma++) ldsm4t(aAddr[ma] + koff, a[ma]);
#pragma unroll
            for (int np = 0; np < 2; np++) ldsm4t(bBase[np] + bOff + koff, bb[np]);
#pragma unroll
            for (int ma = 0; ma < 4; ma++)
#pragma unroll
                for (int np = 0; np < 2; np++) {
                    mma16816(acc[ma][2 * np],     a[ma][0], a[ma][1], a[ma][2], a[ma][3], bb[np][0], bb[np][1]);
                    mma16816(acc[ma][2 * np + 1], a[ma][0], a[ma][1], a[ma][2], a[ma][3], bb[np][2], bb[np][3]);
                }
        }
        __syncthreads();   // all warps done reading kp chunk -> buffer reusable as stage

        // epilogue: exp -> stage into retiring buffer + fused col sums
        uint32_t* stage = dsm + 8704 + buf * 8704;
        float s0[4] = {}, s1[4] = {};
#pragma unroll
        for (int ma = 0; ma < 4; ma++) {
            int r0 = wm * 64 + ma * 16 + lr;
#pragma unroll
            for (int na = 0; na < 4; na++) {
                int cw = wn * 16 + na * 4 + lk;
                float e00 = fexp(acc[ma][na][0]), e01 = fexp(acc[ma][na][1]);
                float e10 = fexp(acc[ma][na][2]), e11 = fexp(acc[ma][na][3]);
                stage[r0 * 68 + cw]       = pack_bf2(e00, e01);
                stage[(r0 + 8) * 68 + cw] = pack_bf2(e10, e11);
                s0[na] += e00 + e10;
                s1[na] += e01 + e11;
            }
        }
#pragma unroll
        for (int na = 0; na < 4; na++) {
#pragma unroll
            for (int off = 4; off < 32; off <<= 1) {
                s0[na] += __shfl_xor_sync(0xffffffffu, s0[na], off);
                s1[na] += __shfl_xor_sync(0xffffffffu, s1[na], off);
            }
        }
        if (lane < 4) {
#pragma unroll
            for (int na = 0; na < 4; na++) {
                int col = mc * 128 + wn * 32 + na * 8 + lane * 2;
                atomicAdd(&g_sum[b * NN + col], s0[na]);
                atomicAdd(&g_sum[b * NN + col + 1], s1[na]);
            }
        }
        __syncthreads();   // stage complete

        size_t ebase = ((size_t)(b * NN + n0)) << 9;
        int mq = mc * 16;
#pragma unroll
        for (int i = 0; i < 8; i++) {
            int idx = tid + i * 256;
            int row = idx >> 4, qx = idx & 15;
            gE4[ebase + ((size_t)row << 9) + mq + qx] = *(uint4*)&stage[row * 68 + qx * 4];
        }
        // no trailing barrier: next-iter top barrier gates reuse of this stage buffer
    }
}

// ================================================================================
// K3: vpT[b,d,m] *= 1/sum[b,m]   (rinv fused)
// ================================================================================
__global__ void __launch_bounds__(256) vscale_kernel()
{
    int idx = blockIdx.x * 256 + threadIdx.x;          // 1M threads, 4 bf16 each
    int e4 = idx << 2;
    int b = e4 >> 19;                                  // / (ND*NN)
    int m = e4 & (NN - 1);
    uint2 w = *(uint2*)&g_vpT[e4];
    float4 s4 = *(const float4*)&g_sum[b * NN + m];
    __nv_bfloat162 p0 = *(__nv_bfloat162*)&w.x;
    __nv_bfloat162 p1 = *(__nv_bfloat162*)&w.y;
    float2 f0 = __bfloat1622float2(p0);
    float2 f1 = __bfloat1622float2(p1);
    uint2 o;
    o.x = pack_bf2(f0.x / s4.x, f0.y / s4.y);
    o.y = pack_bf2(f1.x / s4.z, f1.y / s4.w);
    *(uint2*)&g_vpT[e4] = o;
}

// ================================================================================
// K4: avh[n][d] = sum_m E[n][m] * vpT[d][m]   (K=4096, 3-stage cp.async,
// SINGLE barrier per iteration; prefetch issued after the barrier)
// smem: 3 stages x (A 18432 + B 18432) = 110592 B
// ================================================================================
__global__ void __launch_bounds__(256, 2) pv_kernel()
{
    extern __shared__ uint32_t dsm[];
    int tid = threadIdx.x;
    int wid = tid >> 5, lane = tid & 31;
    int wm = wid & 1, wn = wid >> 1;
    int lr = lane >> 2, lk = lane & 3;
    int lg = lane >> 3, li = lane & 7;
    int n0 = blockIdx.x * 128, b = blockIdx.y;
    const __nv_bfloat16* Eb = g_E   + (size_t)b * NN * NN;
    const __nv_bfloat16* vt = g_vpT + (size_t)b * ND * NN;
    uint32_t sb = smem_u32(dsm);

    float acc[4][4][4] = {};

    // ldmatrix lane base offsets (bytes, within a stage)
    uint32_t aBase[4], bBase[2];
#pragma unroll
    for (int ma = 0; ma < 4; ma++)
        aBase[ma] = (uint32_t)(wm * 64 + ma * 16 + ((lg & 1) << 3) + li) * (KW64 * 4) + ((lg >> 1) << 4);
#pragma unroll
    for (int np = 0; np < 2; np++)
        bBase[np] = 18432u + (uint32_t)(wn * 32 + np * 16 + ((lg >> 1) << 3) + li) * (KW64 * 4) + ((lg & 1) << 4);

    auto issue = [&](int stg, int m0) {
        uint32_t aB = sb + (uint32_t)stg * 36864u;
        uint32_t bB = aB + 18432u;
#pragma unroll
        for (int i = 0; i < 4; i++) {
            int idx = tid + i * 256;
            int row = idx >> 3, qx = idx & 7;
            cpa16(aB + (uint32_t)(row * KW64 + qx * 4) * 4, Eb + (size_t)(n0 + row) * NN + m0 + qx * 8);
            cpa16(bB + (uint32_t)(row * KW64 + qx * 4) * 4, vt + (size_t)row * NN + m0 + qx * 8);
        }
        CP_COMMIT();
    };

    issue(0, 0);
    issue(1, 64);
    int stg = 0;
    for (int it = 0; it < 64; it++) {
        if (it < 63) { CP_WAIT(1); } else { CP_WAIT(0); }
        __syncthreads();                 // stage(it) visible; all reads of stage(it-1) done
        if (it + 2 < 64) issue((it + 2) % 3, (it + 2) * 64);   // overwrites stage(it-1)

        uint32_t sOff = sb + (uint32_t)stg * 36864u;
#pragma unroll
        for (int ks = 0; ks < 4; ks++) {
            uint32_t koff = (uint32_t)ks * 32;
            uint32_t a[4][4], bb[2][4];
#pragma unroll
            for (int ma = 0; ma < 4; ma++) ldsm4(sOff + aBase[ma] + koff, a[ma]);
#pragma unroll
            for (int np = 0; np < 2; np++) ldsm4(sOff + bBase[np] + koff, bb[np]);
#pragma unroll
            for (int ma = 0; ma < 4; ma++)
#pragma unroll
                for (int np = 0; np < 2; np++) {
                    mma16816(acc[ma][2 * np],     a[ma][0], a[ma][1], a[ma][2], a[ma][3], bb[np][0], bb[np][1]);
                    mma16816(acc[ma][2 * np + 1], a[ma][0], a[ma][1], a[ma][2], a[ma][3], bb[np][2], bb[np][3]);
                }
        }
        stg = (stg + 1) % 3;
    }

    // epilogue: bf16 [n][d] direct stores
    uint32_t* ob = (uint32_t*)(g_avh + ((size_t)b * NN + n0) * ND);
#pragma unroll
    for (int ma = 0; ma < 4; ma++) {
        int r0 = wm * 64 + ma * 16 + lr;
#pragma unroll
        for (int na = 0; na < 4; na++) {
            int cw = wn * 16 + na * 4 + lk;
            ob[(size_t)r0 * (ND / 2) + cw]       = pack_bf2(acc[ma][na][0], acc[ma][na][1]);
            ob[(size_t)(r0 + 8) * (ND / 2) + cw] = pack_bf2(acc[ma][na][2], acc[ma][na][3]);
        }
    }
}

// ================================================================================
// K5: y[c][n] = v[c][n] + sum_d Wo[c][d] * avh[n][d]   (unchanged)
// ================================================================================
__global__ void __launch_bounds__(256, 2) final_kernel(const float* __restrict__ vin,
                                                       const float* __restrict__ Wo,
                                                       float* __restrict__ y)
{
    extern __shared__ uint32_t dsm[];
    uint32_t* Asm = dsm;              // Wo tile [c=128][d=128]
    uint32_t* Bsm = dsm + TILE128;    // avh tile [n=128][d=128]

    int tid = threadIdx.x;
    int wid = tid >> 5, lane = tid & 31;
    int wm = wid & 1, wn = wid >> 1;
    int lr = lane >> 2, lk = lane & 3;
    int n0 = blockIdx.x * 128, c0 = blockIdx.y * 128, b = blockIdx.z;
    const __nv_bfloat16* ab = g_avh + ((size_t)b * NN + n0) * ND;

#pragma unroll
    for (int i = 0; i < 16; i++) {
        int idx = tid + i * 256;
        int row = idx >> 5, dq = idx & 31;
        float4 w4 = *(const float4*)(Wo + (size_t)(c0 + row) * ND + dq * 4);
        Asm[row * KW128 + dq * 2]     = pack_bf2(w4.x, w4.y);
        Asm[row * KW128 + dq * 2 + 1] = pack_bf2(w4.z, w4.w);
    }
#pragma unroll
    for (int i = 0; i < 8; i++) {
        int idx = tid + i * 256;
        int row = idx >> 4, qx = idx & 15;
        *(uint4*)&Bsm[row * KW128 + qx * 4] = *(const uint4*)(ab + (size_t)row * ND + qx * 8);
    }
    __syncthreads();

    float acc[4][4][4] = {};
#pragma unroll
    for (int ks = 0; ks < 8; ks++) {
        int k0w = ks * 8;
        uint32_t a[4][4], bb[4][2];
#pragma unroll
        for (int ma = 0; ma < 4; ma++) {
            int w = (wm * 64 + ma * 16 + lr) * KW128 + k0w + lk;
            a[ma][0] = Asm[w];            a[ma][1] = Asm[w + 8 * KW128];
            a[ma][2] = Asm[w + 4];        a[ma][3] = Asm[w + 8 * KW128 + 4];
        }
#pragma unroll
        for (int na = 0; na < 4; na++) {
            int w = (wn * 32 + na * 8 + lr) * KW128 + k0w + lk;
            bb[na][0] = Bsm[w];           bb[na][1] = Bsm[w + 4];
        }
#pragma unroll
        for (int ma = 0; ma < 4; ma++)
#pragma unroll
            for (int na = 0; na < 4; na++)
                mma16816(acc[ma][na], a[ma][0], a[ma][1], a[ma][2], a[ma][3],
                         bb[na][0], bb[na][1]);
    }

    const float* vb = vin + ((size_t)b * NC + c0) * NN + n0;
    float*       yb = y   + ((size_t)b * NC + c0) * NN + n0;
#pragma unroll
    for (int ma = 0; ma < 4; ma++) {
        int r0 = wm * 64 + ma * 16 + lr;
#pragma unroll
        for (int na = 0; na < 4; na++) {
            int c = wn * 32 + na * 8 + lk * 2;
            float2 v0 = *(const float2*)(vb + (size_t)r0 * NN + c);
            float2 v1 = *(const float2*)(vb + (size_t)(r0 + 8) * NN + c);
            *(float2*)(yb + (size_t)r0 * NN + c)       = make_float2(acc[ma][na][0] + v0.x, acc[ma][na][1] + v0.y);
            *(float2*)(yb + (size_t)(r0 + 8) * NN + c) = make_float2(acc[ma][na][2] + v1.x, acc[ma][na][3] + v1.y);
        }
    }
}

// ================================================================================
extern "C" void kernel_launch(void* const* d_in, const int* in_sizes, int n_in,
                              void* d_out, int out_size)
{
    const float* q  = (const float*)d_in[0];
    const float* k  = (const float*)d_in[1];
    const float* v  = (const float*)d_in[2];
    const float* Wt = (const float*)d_in[3];
    const float* Wp = (const float*)d_in[4];
    const float* Wg = (const float*)d_in[5];
    const float* Wo = (const float*)d_in[6];
    float* y = (float*)d_out;

    cudaFuncSetAttribute(proj_kernel,  cudaFuncAttributeMaxDynamicSharedMemorySize, 2 * TILE128 * 4);
    cudaFuncSetAttribute(s_kernel,     cudaFuncAttributeMaxDynamicSharedMemorySize, 3 * TILE128 * 4);
    cudaFuncSetAttribute(pv_kernel,    cudaFuncAttributeMaxDynamicSharedMemorySize, 6 * TILE64 * 4);
    cudaFuncSetAttribute(final_kernel, cudaFuncAttributeMaxDynamicSharedMemorySize, 2 * TILE128 * 4);

    void* sumAddr = nullptr;
    cudaGetSymbolAddress(&sumAddr, g_sum);
    cudaMemsetAsync(sumAddr, 0, NB * NN * sizeof(float));

    proj_kernel  <<<dim3(3, NN / 128, NB), 256, 2 * TILE128 * 4>>>(q, k, v, Wt, Wp, Wg);
    s_kernel     <<<dim3(NN / 128, NB), 256, 3 * TILE128 * 4>>>();
    vscale_kernel<<<dim3((NB * ND * NN / 4) / 256), 256>>>();
    pv_kernel    <<<dim3(NN / 128, NB), 256, 6 * TILE64 * 4>>>();
    final_kernel <<<dim3(NN / 128, NC / 128, NB), 256, 2 * TILE128 * 4>>>(v, Wo, y);
}